// round 2
// baseline (speedup 1.0000x reference)
#include <cuda_runtime.h>
#include <cuda_bf16.h>
#include <math.h>

#define WARP_FULL 0xFFFFFFFFu

// ---------------- scratch (device globals; no allocation) ----------------
__device__ float g_wn0T[64 * 2048];      // [k][o] transposed layer0 weights
__device__ float g_wn1 [2048 * 2048];    // [n][k] layer1 weights (zeros above diag blocks)
__device__ float g_wn2T[2048 * 64];      // [k][o] transposed layer2 weights
__device__ float g_eg0 [2048];           // eg0[d*32+o]   = wn0 diag entries
__device__ float g_eg1 [64 * 32 * 32];   // eg1[d][o][k]  = wn1 diag block entries
__device__ float g_eg2 [64 * 32];        // eg2[d][k]     = wn2 diag entries
__device__ float g_t1 [1024 * 2048];
__device__ float g_tp1[1024 * 2048];
__device__ float g_t2 [1024 * 2048];
__device__ float g_tp2[1024 * 2048];
__device__ float g_h  [1024 * 64];       // raw layer2 output (pre-gate)
__device__ float g_xA [1024 * 64];
__device__ float g_xB [1024 * 64];
__device__ float g_lterm[1024 * 64];     // per-(b,d) ldj contributions, accumulated across flows

// ---------------- weight preprocessing ----------------
// Layer0: W (2048 x 64), ob=32, ib=1. Row r, block d=r/32: col<d -> W, col==d -> exp(W), else 0.
__global__ void prep0_kernel(const float* __restrict__ W, const float* __restrict__ dw) {
    int r = blockIdx.x * 256 + threadIdx.x;
    int blk = r >> 5;
    float s = 0.f;
    for (int c = 0; c < blk; c++) { float wv = W[r * 64 + c]; s += wv * wv; }
    float dv = expf(W[r * 64 + blk]);
    s += dv * dv;
    float scale = expf(dw[r]) / sqrtf(s);
    for (int c = 0; c < 64; c++) {
        float wv;
        if (c < blk)       wv = W[r * 64 + c] * scale;
        else if (c == blk) wv = dv * scale;
        else               wv = 0.f;
        g_wn0T[c * 2048 + r] = wv;
    }
    g_eg0[r] = dv * scale;
}

// Layer1: W (2048 x 2048), ob=ib=32. Warp per row.
__global__ void prep1_kernel(const float* __restrict__ W, const float* __restrict__ dw) {
    int r = blockIdx.x * 8 + (threadIdx.x >> 5);
    int lane = threadIdx.x & 31;
    int blk = r >> 5;
    int d0 = blk * 32, d1 = d0 + 32;
    float s = 0.f;
    for (int c = lane; c < d1; c += 32) {
        float wv = W[r * 2048 + c];
        if (c >= d0) wv = expf(wv);
        s += wv * wv;
    }
    #pragma unroll
    for (int off = 16; off; off >>= 1) s += __shfl_xor_sync(WARP_FULL, s, off);
    float scale = expf(dw[r]) / sqrtf(s);
    for (int c = lane; c < 2048; c += 32) {
        float o;
        if (c < d0) {
            o = W[r * 2048 + c] * scale;
        } else if (c < d1) {
            o = expf(W[r * 2048 + c]) * scale;
            g_eg1[blk * 1024 + (r & 31) * 32 + (c - d0)] = o;
        } else {
            o = 0.f;
        }
        g_wn1[r * 2048 + c] = o;
    }
}

// Layer2: W (64 x 2048), ob=1, ib=32. Warp per row.
__global__ void prep2_kernel(const float* __restrict__ W, const float* __restrict__ dw) {
    int r = blockIdx.x * 8 + (threadIdx.x >> 5);
    int lane = threadIdx.x & 31;
    int d0 = r * 32, d1 = d0 + 32;
    float s = 0.f;
    for (int c = lane; c < d1; c += 32) {
        float wv = W[r * 2048 + c];
        if (c >= d0) wv = expf(wv);
        s += wv * wv;
    }
    #pragma unroll
    for (int off = 16; off; off >>= 1) s += __shfl_xor_sync(WARP_FULL, s, off);
    float scale = expf(dw[r]) / sqrtf(s);
    for (int c = lane; c < 2048; c += 32) {
        float o;
        if (c < d0) {
            o = W[r * 2048 + c] * scale;
        } else if (c < d1) {
            o = expf(W[r * 2048 + c]) * scale;
            g_eg2[r * 32 + (c - d0)] = o;
        } else {
            o = 0.f;
        }
        g_wn2T[c * 64 + r] = o;
    }
}

// ---------------- layer 0: h1 = x @ wn0^T + b0; t1 = tanh, tp1 = 1 - t^2 ----------------
// grid (8, 128), 256 threads. Each block: 256 output cols x 8 batch rows.
__global__ void __launch_bounds__(256) layer0_kernel(const float* __restrict__ xext,
                                                     int xsel,
                                                     const float* __restrict__ bias) {
    __shared__ float xs[8][64];
    const float* xsrc = (xsel == 0) ? xext : ((xsel == 1) ? (const float*)g_xA : (const float*)g_xB);
    int o = blockIdx.x * 256 + threadIdx.x;
    int bbase = blockIdx.y * 8;
    for (int i = threadIdx.x; i < 512; i += 256)
        xs[i >> 6][i & 63] = xsrc[(bbase + (i >> 6)) * 64 + (i & 63)];
    __syncthreads();
    float bv = bias[o];
    float acc[8];
    #pragma unroll
    for (int bi = 0; bi < 8; bi++) acc[bi] = bv;
    #pragma unroll
    for (int k = 0; k < 64; k++) {
        float w = g_wn0T[k * 2048 + o];
        #pragma unroll
        for (int bi = 0; bi < 8; bi++) acc[bi] = fmaf(xs[bi][k], w, acc[bi]);
    }
    #pragma unroll
    for (int bi = 0; bi < 8; bi++) {
        float t = tanhf(acc[bi]);
        g_t1 [(bbase + bi) * 2048 + o] = t;
        g_tp1[(bbase + bi) * 2048 + o] = 1.f - t * t;
    }
}

// ---------------- layer 1 (big GEMM): h2 = t1 @ wn1^T + b1, triangular K limit ----------------
// grid (32 n-tiles, 16 m-tiles), 256 threads, BM=BN=64, BK=32, 4x4 microtile.
__global__ void __launch_bounds__(256) layer1_kernel(const float* __restrict__ bias) {
    __shared__ float As[32][68];   // [k][m], padded; float4-aligned rows
    __shared__ float Bs[32][68];   // [k][n]
    const int m0 = blockIdx.y * 64;
    const int n0 = blockIdx.x * 64;
    const int Klim = n0 + 64;      // block-lower-triangular: cols >= n0+64 are zero
    int tid = threadIdx.x;
    int tx = tid & 15, ty = tid >> 4;
    int lk = tid & 31, lw = tid >> 5;   // loader: lane = k, warp = row group
    float acc[4][4] = {};
    for (int k0 = 0; k0 < Klim; k0 += 32) {
        #pragma unroll
        for (int i = 0; i < 8; i++) {
            int row = lw * 8 + i;
            As[lk][row] = g_t1 [(m0 + row) * 2048 + k0 + lk];
            Bs[lk][row] = g_wn1[(n0 + row) * 2048 + k0 + lk];
        }
        __syncthreads();
        #pragma unroll 8
        for (int kk = 0; kk < 32; kk++) {
            float4 av = *reinterpret_cast<const float4*>(&As[kk][ty * 4]);
            float4 bv = *reinterpret_cast<const float4*>(&Bs[kk][tx * 4]);
            float a[4] = {av.x, av.y, av.z, av.w};
            float b[4] = {bv.x, bv.y, bv.z, bv.w};
            #pragma unroll
            for (int i = 0; i < 4; i++)
                #pragma unroll
                for (int j = 0; j < 4; j++)
                    acc[i][j] = fmaf(a[i], b[j], acc[i][j]);
        }
        __syncthreads();
    }
    #pragma unroll
    for (int i = 0; i < 4; i++) {
        int m = m0 + ty * 4 + i;
        #pragma unroll
        for (int j = 0; j < 4; j++) {
            int n = n0 + tx * 4 + j;
            float v = acc[i][j] + bias[n];
            float t = tanhf(v);
            g_t2 [m * 2048 + n] = t;
            g_tp2[m * 2048 + n] = 1.f - t * t;
        }
    }
}

// ---------------- layer 2: h = t2 @ wn2^T + b2 (1024x64, K=2048) ----------------
// grid 64, 256 threads. Block: 16 batch rows x 64 outputs; thread: 4 batch rows.
__global__ void __launch_bounds__(256) layer2_kernel(const float* __restrict__ bias) {
    __shared__ float ts[16][65];
    int tid = threadIdx.x;
    int o = tid & 63;
    int bq = tid >> 6;           // 0..3
    int bbase = blockIdx.x * 16;
    float acc[4] = {};
    for (int k0 = 0; k0 < 2048; k0 += 64) {
        #pragma unroll
        for (int i = 0; i < 4; i++) {
            int idx = tid + 256 * i;           // 0..1023
            int rr = idx >> 6, cc = idx & 63;
            ts[rr][cc] = g_t2[(bbase + rr) * 2048 + k0 + cc];
        }
        __syncthreads();
        #pragma unroll 16
        for (int k = 0; k < 64; k++) {
            float w = g_wn2T[(k0 + k) * 64 + o];
            #pragma unroll
            for (int j = 0; j < 4; j++)
                acc[j] = fmaf(ts[bq * 4 + j][k], w, acc[j]);
        }
        __syncthreads();
    }
    float bv = bias[o];
    #pragma unroll
    for (int j = 0; j < 4; j++)
        g_h[(bbase + bq * 4 + j) * 64 + o] = acc[j] + bv;
}

// ---------------- Jacobian chain + gate + flip ----------------
// grid (8, 1024), 256 threads: warp per (b, d). Linear-space Jacobian product.
__global__ void __launch_bounds__(256) jac_kernel(const float* __restrict__ xext,
                                                  int xsel, int nsel,
                                                  const float* __restrict__ gate,
                                                  int hasGate, int accum) {
    int b = blockIdx.y;
    int d = blockIdx.x * 8 + (threadIdx.x >> 5);
    int lane = threadIdx.x & 31;

    float v0 = g_eg0[d * 32 + lane] * g_tp1[b * 2048 + d * 32 + lane];
    float acc = 0.f;
    #pragma unroll
    for (int k = 0; k < 32; k++)
        acc = fmaf(g_eg1[d * 1024 + lane * 32 + k], __shfl_sync(WARP_FULL, v0, k), acc);
    float v1 = acc * g_tp2[b * 2048 + d * 32 + lane];
    float term = g_eg2[d * 32 + lane] * v1;
    #pragma unroll
    for (int off = 16; off; off >>= 1) term += __shfl_xor_sync(WARP_FULL, term, off);

    if (lane == 0) {
        float* xnext = (nsel == 1) ? g_xA : g_xB;
        float g = logf(term);
        float outv = g_h[b * 64 + d];
        float l;
        if (hasGate) {
            const float* xcur = (xsel == 0) ? xext : ((xsel == 1) ? (const float*)g_xA : (const float*)g_xB);
            float gt = *gate;
            float z = g + gt;
            float sp1 = (z  > 20.f) ? z  : log1pf(expf(z));
            float sp0 = (gt > 20.f) ? gt : log1pf(expf(gt));
            l = sp1 - sp0;
            float sgm = 1.f / (1.f + expf(-gt));
            float xo = sgm * outv + (1.f - sgm) * xcur[b * 64 + d];
            xnext[b * 64 + (63 - d)] = xo;   // fused flip
        } else {
            l = g;
            xnext[b * 64 + d] = outv;
        }
        if (accum) g_lterm[b * 64 + d] += l;
        else       g_lterm[b * 64 + d]  = l;
    }
}

// ---------------- final: log_p = sum(-0.5 x^2) - 32*log(2pi) + ldj ----------------
__global__ void __launch_bounds__(256) final_kernel(int xsel, float* __restrict__ out) {
    const float* xf = (xsel == 1) ? (const float*)g_xA : (const float*)g_xB;
    int b = blockIdx.x * 8 + (threadIdx.x >> 5);
    int lane = threadIdx.x & 31;
    float v1 = xf[b * 64 + lane];
    float v2 = xf[b * 64 + 32 + lane];
    float s = -0.5f * (v1 * v1 + v2 * v2)
              + g_lterm[b * 64 + lane] + g_lterm[b * 64 + 32 + lane];
    #pragma unroll
    for (int off = 16; off; off >>= 1) s += __shfl_xor_sync(WARP_FULL, s, off);
    if (lane == 0) out[b] = s - 32.f * 1.8378770664093453f;  // 64 * 0.5 * log(2*pi)
}

// ---------------- launch ----------------
extern "C" void kernel_launch(void* const* d_in, const int* in_sizes, int n_in,
                              void* d_out, int out_size) {
    (void)in_sizes; (void)n_in; (void)out_size;
    const float* x     = (const float*)d_in[0];
    const float* gate0 = (const float*)d_in[28];
    const float* gate1 = (const float*)d_in[29];

    int xsel = 0;  // 0: external input, 1: g_xA, 2: g_xB
    for (int f = 0; f < 3; f++) {
        const float* W0  = (const float*)d_in[1 + f * 9 + 0];
        const float* dw0 = (const float*)d_in[1 + f * 9 + 1];
        const float* b0  = (const float*)d_in[1 + f * 9 + 2];
        const float* W1  = (const float*)d_in[1 + f * 9 + 3];
        const float* dw1 = (const float*)d_in[1 + f * 9 + 4];
        const float* b1  = (const float*)d_in[1 + f * 9 + 5];
        const float* W2  = (const float*)d_in[1 + f * 9 + 6];
        const float* dw2 = (const float*)d_in[1 + f * 9 + 7];
        const float* b2  = (const float*)d_in[1 + f * 9 + 8];

        prep0_kernel<<<8,   256>>>(W0, dw0);
        prep1_kernel<<<256, 256>>>(W1, dw1);
        prep2_kernel<<<8,   256>>>(W2, dw2);

        layer0_kernel<<<dim3(8, 128), 256>>>(x, xsel, b0);
        layer1_kernel<<<dim3(32, 16), 256>>>(b1);
        layer2_kernel<<<64, 256>>>(b2);

        const float* gate = (f == 0) ? gate0 : ((f == 1) ? gate1 : nullptr);
        int nsel = (f & 1) ? 2 : 1;   // flow0 -> g_xA, flow1 -> g_xB, flow2 -> g_xA
        jac_kernel<<<dim3(8, 1024), 256>>>(x, xsel, nsel, gate, (f < 2) ? 1 : 0, (f > 0) ? 1 : 0);
        xsel = nsel;
    }
    final_kernel<<<128, 256>>>(xsel, (float*)d_out);
}

// round 3
// speedup vs baseline: 1.9929x; 1.9929x over previous
#include <cuda_runtime.h>
#include <cuda_bf16.h>
#include <math.h>

#define WARP_FULL 0xFFFFFFFFu

// ---------------- scratch (device globals; no allocation) ----------------
__device__ float g_wn0T[64 * 2048];      // [k][o] transposed layer0 weights
__device__ float g_wn1 [2048 * 2048];    // [n][k] layer1 weights (valid for k < ((n/64)+1)*64)
__device__ float g_wn2K[64 * 2048];      // [o][k] row-major layer2 weights
__device__ float g_eg0 [2048];           // eg0[d*32+o]
__device__ float g_eg1 [64 * 32 * 32];   // eg1[d][k][o]  (transposed diag blocks)
__device__ float g_eg2 [64 * 32];        // eg2[d][k]
__device__ float g_t1 [1024 * 2048];
__device__ float g_t2 [1024 * 2048];
__device__ float g_h2 [2 * 1024 * 64];   // layer2 K-split partials (no bias)
__device__ float g_xA [1024 * 64];
__device__ float g_xB [1024 * 64];
__device__ float g_lterm[1024 * 64];

// ---------------- weight preprocessing ----------------
__global__ void prep0_kernel(const float* __restrict__ W, const float* __restrict__ dw) {
    int r = blockIdx.x * 256 + threadIdx.x;
    int blk = r >> 5;
    float s = 0.f;
    for (int c = 0; c < blk; c++) { float wv = W[r * 64 + c]; s += wv * wv; }
    float dv = expf(W[r * 64 + blk]);
    s += dv * dv;
    float scale = expf(dw[r]) / sqrtf(s);
    for (int c = 0; c < 64; c++) {
        float wv;
        if (c < blk)       wv = W[r * 64 + c] * scale;
        else if (c == blk) wv = dv * scale;
        else               wv = 0.f;
        g_wn0T[c * 2048 + r] = wv;
    }
    g_eg0[r] = dv * scale;
}

// Layer1: warp per row; write only the k-band layer1 actually reads.
__global__ void prep1_kernel(const float* __restrict__ W, const float* __restrict__ dw) {
    int r = blockIdx.x * 8 + (threadIdx.x >> 5);
    int lane = threadIdx.x & 31;
    int blk = r >> 5;
    int d0 = blk * 32, d1 = d0 + 32;
    int cmax = ((r >> 6) + 1) << 6;       // = tile Klim for this row
    float s = 0.f;
    for (int c = lane; c < d1; c += 32) {
        float wv = W[r * 2048 + c];
        if (c >= d0) wv = expf(wv);
        s += wv * wv;
    }
    #pragma unroll
    for (int off = 16; off; off >>= 1) s += __shfl_xor_sync(WARP_FULL, s, off);
    float scale = expf(dw[r]) / sqrtf(s);
    for (int c = lane; c < cmax; c += 32) {
        float o;
        if (c < d0) {
            o = W[r * 2048 + c] * scale;
        } else if (c < d1) {
            o = expf(W[r * 2048 + c]) * scale;
            g_eg1[blk * 1024 + (c - d0) * 32 + (r & 31)] = o;   // [d][k][o]
        } else {
            o = 0.f;
        }
        g_wn1[r * 2048 + c] = o;
    }
}

__global__ void prep2_kernel(const float* __restrict__ W, const float* __restrict__ dw) {
    int r = blockIdx.x * 8 + (threadIdx.x >> 5);
    int lane = threadIdx.x & 31;
    int d0 = r * 32, d1 = d0 + 32;
    float s = 0.f;
    for (int c = lane; c < d1; c += 32) {
        float wv = W[r * 2048 + c];
        if (c >= d0) wv = expf(wv);
        s += wv * wv;
    }
    #pragma unroll
    for (int off = 16; off; off >>= 1) s += __shfl_xor_sync(WARP_FULL, s, off);
    float scale = expf(dw[r]) / sqrtf(s);
    for (int c = lane; c < 2048; c += 32) {
        float o;
        if (c < d0) {
            o = W[r * 2048 + c] * scale;
        } else if (c < d1) {
            o = expf(W[r * 2048 + c]) * scale;
            g_eg2[r * 32 + (c - d0)] = o;
        } else {
            o = 0.f;
        }
        g_wn2K[r * 2048 + c] = o;
    }
}

// ---------------- layer 0: t1 = tanh(x @ wn0^T + b0) ----------------
__global__ void __launch_bounds__(256) layer0_kernel(const float* __restrict__ xext,
                                                     int xsel,
                                                     const float* __restrict__ bias) {
    __shared__ float xs[64][8];   // [k][bi], 32B rows (float4-aligned)
    const float* xsrc = (xsel == 0) ? xext : ((xsel == 1) ? (const float*)g_xA : (const float*)g_xB);
    int o = blockIdx.x * 256 + threadIdx.x;
    int bbase = blockIdx.y * 8;
    for (int i = threadIdx.x; i < 512; i += 256) {
        int k = i >> 3, bi = i & 7;               // smem-store conflict-free mapping
        xs[k][bi] = xsrc[(bbase + bi) * 64 + k];
    }
    __syncthreads();
    float bv = bias[o];
    float acc[8];
    #pragma unroll
    for (int bi = 0; bi < 8; bi++) acc[bi] = bv;
    #pragma unroll 16
    for (int k = 0; k < 64; k++) {
        float w = g_wn0T[k * 2048 + o];
        float4 x0 = *reinterpret_cast<const float4*>(&xs[k][0]);
        float4 x1 = *reinterpret_cast<const float4*>(&xs[k][4]);
        acc[0] = fmaf(x0.x, w, acc[0]); acc[1] = fmaf(x0.y, w, acc[1]);
        acc[2] = fmaf(x0.z, w, acc[2]); acc[3] = fmaf(x0.w, w, acc[3]);
        acc[4] = fmaf(x1.x, w, acc[4]); acc[5] = fmaf(x1.y, w, acc[5]);
        acc[6] = fmaf(x1.z, w, acc[6]); acc[7] = fmaf(x1.w, w, acc[7]);
    }
    #pragma unroll
    for (int bi = 0; bi < 8; bi++)
        g_t1[(bbase + bi) * 2048 + o] = tanhf(acc[bi]);
}

// ---------------- layer 1: t2 = tanh(t1 @ wn1^T + b1), triangular ----------------
// BM=BN=64, BK=32, 128 threads, 8x4 microtile. Deepest n-tiles first.
__global__ void __launch_bounds__(128) layer1_kernel(const float* __restrict__ bias) {
    __shared__ float As[32][68];   // [k][m]
    __shared__ float Bs[32][68];   // [k][n]
    const int nt = 31 - blockIdx.x;
    const int m0 = blockIdx.y * 64;
    const int n0 = nt * 64;
    const int Klim = n0 + 64;
    const int tid = threadIdx.x;
    const int tx = tid & 15;      // n = n0 + tx*4 + j
    const int ty = tid >> 4;      // m = m0 + ty*8 + i
    float acc[8][4] = {};
    for (int k0 = 0; k0 < Klim; k0 += 32) {
        #pragma unroll
        for (int i = 0; i < 4; i++) {
            int idx = tid * 4 + i;          // 0..511
            int m = idx >> 3;
            int kq = idx & 7;
            float4 v = *reinterpret_cast<const float4*>(&g_t1[(m0 + m) * 2048 + k0 + kq * 4]);
            As[kq*4+0][m] = v.x; As[kq*4+1][m] = v.y; As[kq*4+2][m] = v.z; As[kq*4+3][m] = v.w;
        }
        #pragma unroll
        for (int i = 0; i < 4; i++) {
            int idx = tid * 4 + i;
            int n = idx >> 3;
            int kq = idx & 7;
            float4 v = *reinterpret_cast<const float4*>(&g_wn1[(n0 + n) * 2048 + k0 + kq * 4]);
            Bs[kq*4+0][n] = v.x; Bs[kq*4+1][n] = v.y; Bs[kq*4+2][n] = v.z; Bs[kq*4+3][n] = v.w;
        }
        __syncthreads();
        #pragma unroll 8
        for (int kk = 0; kk < 32; kk++) {
            float4 a0 = *reinterpret_cast<const float4*>(&As[kk][ty * 8]);
            float4 a1 = *reinterpret_cast<const float4*>(&As[kk][ty * 8 + 4]);
            float4 b4 = *reinterpret_cast<const float4*>(&Bs[kk][tx * 4]);
            float a[8] = {a0.x, a0.y, a0.z, a0.w, a1.x, a1.y, a1.z, a1.w};
            float b[4] = {b4.x, b4.y, b4.z, b4.w};
            #pragma unroll
            for (int i = 0; i < 8; i++)
                #pragma unroll
                for (int j = 0; j < 4; j++)
                    acc[i][j] = fmaf(a[i], b[j], acc[i][j]);
        }
        __syncthreads();
    }
    float bv[4];
    #pragma unroll
    for (int j = 0; j < 4; j++) bv[j] = bias[n0 + tx * 4 + j];
    #pragma unroll
    for (int i = 0; i < 8; i++) {
        int m = m0 + ty * 8 + i;
        float4 o;
        o.x = tanhf(acc[i][0] + bv[0]);
        o.y = tanhf(acc[i][1] + bv[1]);
        o.z = tanhf(acc[i][2] + bv[2]);
        o.w = tanhf(acc[i][3] + bv[3]);
        *reinterpret_cast<float4*>(&g_t2[m * 2048 + n0 + tx * 4]) = o;
    }
}

// ---------------- layer 2: h2 partials = t2 @ wn2^T (K-split x2, bias in jac) ----------------
__global__ void __launch_bounds__(256) layer2_kernel() {
    __shared__ float ts[16][68];
    int tid = threadIdx.x;
    int o = tid & 63;
    int bq = tid >> 6;
    int bbase = blockIdx.x * 16;
    int kbase = blockIdx.y * 1024;
    float acc[4] = {};
    for (int k0 = kbase; k0 < kbase + 1024; k0 += 64) {
        {
            int rr = tid >> 4, cq = tid & 15;
            float4 v = *reinterpret_cast<const float4*>(&g_t2[(bbase + rr) * 2048 + k0 + cq * 4]);
            *reinterpret_cast<float4*>(&ts[rr][cq * 4]) = v;
        }
        __syncthreads();
        #pragma unroll
        for (int kq = 0; kq < 16; kq++) {
            float4 w = *reinterpret_cast<const float4*>(&g_wn2K[o * 2048 + k0 + kq * 4]);
            #pragma unroll
            for (int j = 0; j < 4; j++) {
                float4 t = *reinterpret_cast<const float4*>(&ts[bq * 4 + j][kq * 4]);
                acc[j] = fmaf(w.x, t.x, acc[j]);
                acc[j] = fmaf(w.y, t.y, acc[j]);
                acc[j] = fmaf(w.z, t.z, acc[j]);
                acc[j] = fmaf(w.w, t.w, acc[j]);
            }
        }
        __syncthreads();
    }
    #pragma unroll
    for (int j = 0; j < 4; j++)
        g_h2[blockIdx.y * 65536 + (bbase + bq * 4 + j) * 64 + o] = acc[j];
}

// ---------------- Jacobian chain + gate + flip ----------------
// grid (64 d, 8 bslice), 256 threads; eg1 block staged in smem.
__global__ void __launch_bounds__(256) jac_kernel(const float* __restrict__ xext,
                                                  int xsel, int nsel,
                                                  const float* __restrict__ gate,
                                                  int hasGate, int accum,
                                                  const float* __restrict__ b2) {
    __shared__ float eg1s[1024];
    __shared__ float eg0s[32];
    __shared__ float eg2s[32];
    int d = blockIdx.x;
    int lane = threadIdx.x & 31, w = threadIdx.x >> 5;
    for (int i = threadIdx.x; i < 1024; i += 256) eg1s[i] = g_eg1[d * 1024 + i];
    if (threadIdx.x < 32) {
        eg0s[threadIdx.x] = g_eg0[d * 32 + threadIdx.x];
        eg2s[threadIdx.x] = g_eg2[d * 32 + threadIdx.x];
    }
    __syncthreads();
    const float* xcur = (xsel == 0) ? xext : ((xsel == 1) ? (const float*)g_xA : (const float*)g_xB);
    float* xnext = (nsel == 1) ? g_xA : g_xB;
    float gt = 0.f;
    if (hasGate) gt = *gate;
    float bias_d = b2[d];

    for (int bi = 0; bi < 16; bi++) {
        int b = blockIdx.y * 128 + bi * 8 + w;
        float t1v = g_t1[b * 2048 + d * 32 + lane];
        float v0 = eg0s[lane] * (1.f - t1v * t1v);
        float acc = 0.f;
        #pragma unroll
        for (int k = 0; k < 32; k++)
            acc = fmaf(eg1s[k * 32 + lane], __shfl_sync(WARP_FULL, v0, k), acc);
        float t2v = g_t2[b * 2048 + d * 32 + lane];
        float term = eg2s[lane] * acc * (1.f - t2v * t2v);
        #pragma unroll
        for (int off = 16; off; off >>= 1) term += __shfl_xor_sync(WARP_FULL, term, off);

        if (lane == 0) {
            float g = logf(term);
            float outv = g_h2[b * 64 + d] + g_h2[65536 + b * 64 + d] + bias_d;
            float l;
            if (hasGate) {
                float z = g + gt;
                float sp1 = (z  > 20.f) ? z  : log1pf(expf(z));
                float sp0 = (gt > 20.f) ? gt : log1pf(expf(gt));
                l = sp1 - sp0;
                float sgm = 1.f / (1.f + expf(-gt));
                xnext[b * 64 + (63 - d)] = sgm * outv + (1.f - sgm) * xcur[b * 64 + d];
            } else {
                l = g;
                xnext[b * 64 + d] = outv;
            }
            if (accum) g_lterm[b * 64 + d] += l;
            else       g_lterm[b * 64 + d]  = l;
        }
    }
}

// ---------------- final reduction ----------------
__global__ void __launch_bounds__(256) final_kernel(int xsel, float* __restrict__ out) {
    const float* xf = (xsel == 1) ? (const float*)g_xA : (const float*)g_xB;
    int b = blockIdx.x * 8 + (threadIdx.x >> 5);
    int lane = threadIdx.x & 31;
    float v1 = xf[b * 64 + lane];
    float v2 = xf[b * 64 + 32 + lane];
    float s = -0.5f * (v1 * v1 + v2 * v2)
              + g_lterm[b * 64 + lane] + g_lterm[b * 64 + 32 + lane];
    #pragma unroll
    for (int off = 16; off; off >>= 1) s += __shfl_xor_sync(WARP_FULL, s, off);
    if (lane == 0) out[b] = s - 32.f * 1.8378770664093453f;
}

// ---------------- launch ----------------
extern "C" void kernel_launch(void* const* d_in, const int* in_sizes, int n_in,
                              void* d_out, int out_size) {
    (void)in_sizes; (void)n_in; (void)out_size;
    const float* x     = (const float*)d_in[0];
    const float* gate0 = (const float*)d_in[28];
    const float* gate1 = (const float*)d_in[29];

    int xsel = 0;
    for (int f = 0; f < 3; f++) {
        const float* W0  = (const float*)d_in[1 + f * 9 + 0];
        const float* dw0 = (const float*)d_in[1 + f * 9 + 1];
        const float* b0  = (const float*)d_in[1 + f * 9 + 2];
        const float* W1  = (const float*)d_in[1 + f * 9 + 3];
        const float* dw1 = (const float*)d_in[1 + f * 9 + 4];
        const float* b1  = (const float*)d_in[1 + f * 9 + 5];
        const float* W2  = (const float*)d_in[1 + f * 9 + 6];
        const float* dw2 = (const float*)d_in[1 + f * 9 + 7];
        const float* b2  = (const float*)d_in[1 + f * 9 + 8];

        prep0_kernel<<<8,   256>>>(W0, dw0);
        prep1_kernel<<<256, 256>>>(W1, dw1);
        prep2_kernel<<<8,   256>>>(W2, dw2);

        layer0_kernel<<<dim3(8, 128), 256>>>(x, xsel, b0);
        layer1_kernel<<<dim3(32, 16), 128>>>(b1);
        layer2_kernel<<<dim3(64, 2), 256>>>();

        const float* gate = (f == 0) ? gate0 : ((f == 1) ? gate1 : nullptr);
        int nsel = (f & 1) ? 2 : 1;
        jac_kernel<<<dim3(64, 8), 256>>>(x, xsel, nsel, gate, (f < 2) ? 1 : 0, (f > 0) ? 1 : 0, b2);
        xsel = nsel;
    }
    final_kernel<<<128, 256>>>(xsel, (float*)d_out);
}

// round 4
// speedup vs baseline: 2.8759x; 1.4431x over previous
#include <cuda_runtime.h>
#include <cuda_bf16.h>
#include <math.h>

#define WARP_FULL 0xFFFFFFFFu

// ---------------- scratch (device globals; no allocation) ----------------
__device__ float g_wn0T[3][64 * 2048];     // [f][k][o]
__device__ float g_wn1 [3][2048 * 2048];   // [f][n][k] (band k < ((n/64)+1)*64 valid)
__device__ float g_wn2K[3][64 * 2048];     // [f][o][k]
__device__ float g_eg0 [3][2048];
__device__ float g_eg1 [3][64 * 32 * 32];  // [f][d][k][o]
__device__ float g_eg2 [3][64 * 32];
__device__ float g_t1 [1024 * 2048];
__device__ float g_t2 [1024 * 2048];
__device__ float g_part[2048 * 128 * 64];  // [slot][m][n] layer1 K-split partials (64MB)
__device__ float g_h2 [2 * 1024 * 64];
__device__ float g_xA [1024 * 64];
__device__ float g_xB [1024 * 64];
__device__ float g_lterm[1024 * 64];

struct PrepPtrs { const float* W[9]; const float* dw[9]; };  // [f*3 + layer]

// ---------------- merged weight preprocessing: warp per row ----------------
// grid (520, 3), 256 threads. wr<2048: layer0 row; wr<4096: layer1; else layer2.
__global__ void __launch_bounds__(256) prep_all_kernel(PrepPtrs P) {
    int f = blockIdx.y;
    int wr = blockIdx.x * 8 + (threadIdx.x >> 5);
    int lane = threadIdx.x & 31;

    if (wr < 2048) {                        // ---- layer0: W (2048 x 64), ob=32, ib=1
        const float* W  = P.W [f * 3 + 0];
        const float* dw = P.dw[f * 3 + 0];
        int r = wr, blk = r >> 5;
        float vals[2]; float s = 0.f;
        #pragma unroll
        for (int i = 0; i < 2; i++) {
            int c = lane + 32 * i;
            float raw = W[r * 64 + c];
            float v = (c < blk) ? raw : ((c == blk) ? expf(raw) : 0.f);
            vals[i] = v; s += v * v;
        }
        #pragma unroll
        for (int off = 16; off; off >>= 1) s += __shfl_xor_sync(WARP_FULL, s, off);
        float scale = expf(dw[r]) * rsqrtf(s);
        #pragma unroll
        for (int i = 0; i < 2; i++) {
            int c = lane + 32 * i;
            float wv = vals[i] * scale;
            g_wn0T[f][c * 2048 + r] = wv;
            if (c == blk) g_eg0[f][r] = wv;
        }
    } else if (wr < 4096) {                 // ---- layer1: W (2048 x 2048), ob=ib=32
        const float* W  = P.W [f * 3 + 1];
        const float* dw = P.dw[f * 3 + 1];
        int r = wr - 2048, blk = r >> 5;
        int d0 = blk * 32, d1 = d0 + 32;
        int cmax = ((r >> 6) + 1) << 6;
        float s = 0.f;
        for (int c = lane; c < d1; c += 32) {
            float wv = W[r * 2048 + c];
            if (c >= d0) wv = expf(wv);
            s += wv * wv;
        }
        #pragma unroll
        for (int off = 16; off; off >>= 1) s += __shfl_xor_sync(WARP_FULL, s, off);
        float scale = expf(dw[r]) * rsqrtf(s);
        for (int c = lane; c < cmax; c += 32) {
            float o;
            if (c < d0)       o = W[r * 2048 + c] * scale;
            else if (c < d1) {
                o = expf(W[r * 2048 + c]) * scale;
                g_eg1[f][blk * 1024 + (c - d0) * 32 + (r & 31)] = o;
            } else            o = 0.f;
            g_wn1[f][r * 2048 + c] = o;
        }
    } else {                                // ---- layer2: W (64 x 2048), ob=1, ib=32
        const float* W  = P.W [f * 3 + 2];
        const float* dw = P.dw[f * 3 + 2];
        int r = wr - 4096;
        int d0 = r * 32, d1 = d0 + 32;
        float s = 0.f;
        for (int c = lane; c < d1; c += 32) {
            float wv = W[r * 2048 + c];
            if (c >= d0) wv = expf(wv);
            s += wv * wv;
        }
        #pragma unroll
        for (int off = 16; off; off >>= 1) s += __shfl_xor_sync(WARP_FULL, s, off);
        float scale = expf(dw[r]) * rsqrtf(s);
        for (int c = lane; c < 2048; c += 32) {
            float o;
            if (c < d0)       o = W[r * 2048 + c] * scale;
            else if (c < d1) {
                o = expf(W[r * 2048 + c]) * scale;
                g_eg2[f][r * 32 + (c - d0)] = o;
            } else            o = 0.f;
            g_wn2K[f][r * 2048 + c] = o;
        }
    }
}

// ---------------- layer 0: t1 = tanh(x @ wn0^T + b0) ----------------
__global__ void __launch_bounds__(256) layer0_kernel(const float* __restrict__ xext,
                                                     int xsel, int f,
                                                     const float* __restrict__ bias) {
    __shared__ float xs[64][8];
    const float* xsrc = (xsel == 0) ? xext : ((xsel == 1) ? (const float*)g_xA : (const float*)g_xB);
    int o = blockIdx.x * 256 + threadIdx.x;
    int bbase = blockIdx.y * 8;
    for (int i = threadIdx.x; i < 512; i += 256) {
        int k = i >> 3, bi = i & 7;
        xs[k][bi] = xsrc[(bbase + bi) * 64 + k];
    }
    __syncthreads();
    const float* wn0T = g_wn0T[f];
    float bv = bias[o];
    float acc[8];
    #pragma unroll
    for (int bi = 0; bi < 8; bi++) acc[bi] = bv;
    #pragma unroll 16
    for (int k = 0; k < 64; k++) {
        float w = wn0T[k * 2048 + o];
        float4 x0 = *reinterpret_cast<const float4*>(&xs[k][0]);
        float4 x1 = *reinterpret_cast<const float4*>(&xs[k][4]);
        acc[0] = fmaf(x0.x, w, acc[0]); acc[1] = fmaf(x0.y, w, acc[1]);
        acc[2] = fmaf(x0.z, w, acc[2]); acc[3] = fmaf(x0.w, w, acc[3]);
        acc[4] = fmaf(x1.x, w, acc[4]); acc[5] = fmaf(x1.y, w, acc[5]);
        acc[6] = fmaf(x1.z, w, acc[6]); acc[7] = fmaf(x1.w, w, acc[7]);
    }
    #pragma unroll
    for (int bi = 0; bi < 8; bi++)
        g_t1[(bbase + bi) * 2048 + o] = tanhf(acc[bi]);
}

// ---------------- layer 1 K-split GEMM: partials = t1 @ wn1^T ----------------
// grid (32 nt, 8 mt, 8 chunk), 256 threads. BM=128, BN=64, BK=16, 8x4 microtile.
// Chunk ch covers k in [ch*256, min(ch*256+256, (nt+1)*64)); inactive chunks exit.
__global__ void __launch_bounds__(256) layer1_kernel(int f) {
    const int nt = blockIdx.x, mt = blockIdx.y, ch = blockIdx.z;
    const int Klim = (nt + 1) * 64;
    const int kbeg = ch * 256;
    if (kbeg >= Klim) return;
    const int kend = min(kbeg + 256, Klim);
    const int m0 = mt * 128, n0 = nt * 64;
    const float* wn1f = g_wn1[f];

    __shared__ float As[2][16][132];
    __shared__ float Bs[2][16][68];

    const int tid = threadIdx.x;
    const int tx = tid & 15;      // n = n0 + tx*4 + j
    const int ty = tid >> 4;      // m = m0 + ty*8 + i
    const int lm = tid >> 2;      // loader row (A: m, B: n uses tid>>2 & 63)
    const int lkq = tid & 3;      // loader k-quad

    float4 pa0, pa1, pb;
    float acc[8][4] = {};

    // preload first tile
    pa0 = *reinterpret_cast<const float4*>(&g_t1[(m0 + lm) * 2048 + kbeg + lkq * 4]);
    pa1 = *reinterpret_cast<const float4*>(&g_t1[(m0 + lm + 64) * 2048 + kbeg + lkq * 4]);
    pb  = *reinterpret_cast<const float4*>(&wn1f[(n0 + (lm & 63)) * 2048 + kbeg + lkq * 4]);
    {
        As[0][lkq*4+0][lm] = pa0.x; As[0][lkq*4+1][lm] = pa0.y;
        As[0][lkq*4+2][lm] = pa0.z; As[0][lkq*4+3][lm] = pa0.w;
        As[0][lkq*4+0][lm+64] = pa1.x; As[0][lkq*4+1][lm+64] = pa1.y;
        As[0][lkq*4+2][lm+64] = pa1.z; As[0][lkq*4+3][lm+64] = pa1.w;
        Bs[0][lkq*4+0][lm&63] = pb.x; Bs[0][lkq*4+1][lm&63] = pb.y;
        Bs[0][lkq*4+2][lm&63] = pb.z; Bs[0][lkq*4+3][lm&63] = pb.w;
    }
    __syncthreads();

    int buf = 0;
    for (int kb = kbeg; kb < kend; kb += 16) {
        bool more = (kb + 16) < kend;
        if (more) {
            pa0 = *reinterpret_cast<const float4*>(&g_t1[(m0 + lm) * 2048 + kb + 16 + lkq * 4]);
            pa1 = *reinterpret_cast<const float4*>(&g_t1[(m0 + lm + 64) * 2048 + kb + 16 + lkq * 4]);
            pb  = *reinterpret_cast<const float4*>(&wn1f[(n0 + (lm & 63)) * 2048 + kb + 16 + lkq * 4]);
        }
        #pragma unroll
        for (int kk = 0; kk < 16; kk++) {
            float4 a0 = *reinterpret_cast<const float4*>(&As[buf][kk][ty * 8]);
            float4 a1 = *reinterpret_cast<const float4*>(&As[buf][kk][ty * 8 + 4]);
            float4 b4 = *reinterpret_cast<const float4*>(&Bs[buf][kk][tx * 4]);
            float a[8] = {a0.x, a0.y, a0.z, a0.w, a1.x, a1.y, a1.z, a1.w};
            float b[4] = {b4.x, b4.y, b4.z, b4.w};
            #pragma unroll
            for (int i = 0; i < 8; i++)
                #pragma unroll
                for (int j = 0; j < 4; j++)
                    acc[i][j] = fmaf(a[i], b[j], acc[i][j]);
        }
        if (more) {
            int nb = buf ^ 1;
            As[nb][lkq*4+0][lm] = pa0.x; As[nb][lkq*4+1][lm] = pa0.y;
            As[nb][lkq*4+2][lm] = pa0.z; As[nb][lkq*4+3][lm] = pa0.w;
            As[nb][lkq*4+0][lm+64] = pa1.x; As[nb][lkq*4+1][lm+64] = pa1.y;
            As[nb][lkq*4+2][lm+64] = pa1.z; As[nb][lkq*4+3][lm+64] = pa1.w;
            Bs[nb][lkq*4+0][lm&63] = pb.x; Bs[nb][lkq*4+1][lm&63] = pb.y;
            Bs[nb][lkq*4+2][lm&63] = pb.z; Bs[nb][lkq*4+3][lm&63] = pb.w;
        }
        __syncthreads();
        buf ^= 1;
    }

    float* out = &g_part[(size_t)(((nt * 8 + ch) * 8 + mt)) * 8192];
    #pragma unroll
    for (int i = 0; i < 8; i++) {
        float4 v = make_float4(acc[i][0], acc[i][1], acc[i][2], acc[i][3]);
        *reinterpret_cast<float4*>(&out[(ty * 8 + i) * 64 + tx * 4]) = v;
    }
}

// ---------------- layer1 reduce: t2 = tanh(sum partials + b1) ----------------
// grid (32 nt, 8 mt), 256 threads.
__global__ void __launch_bounds__(256) reduce1_kernel(const float* __restrict__ bias) {
    const int nt = blockIdx.x, mt = blockIdx.y;
    const int Cnt = (nt + 4) >> 2;   // ceil((nt+1)*64 / 256)
    const int m0 = mt * 128, n0 = nt * 64;
    const float* base = &g_part[(size_t)((nt * 8) * 8 + mt) * 8192];
    for (int e = threadIdx.x * 4; e < 8192; e += 1024) {
        float4 s = *reinterpret_cast<const float4*>(&base[e]);
        for (int c = 1; c < Cnt; c++) {
            float4 p = *reinterpret_cast<const float4*>(&base[(size_t)c * 65536 + e]);
            s.x += p.x; s.y += p.y; s.z += p.z; s.w += p.w;
        }
        int m = e >> 6, n = e & 63;
        float4 bv = *reinterpret_cast<const float4*>(&bias[n0 + n]);
        float4 o;
        o.x = tanhf(s.x + bv.x); o.y = tanhf(s.y + bv.y);
        o.z = tanhf(s.z + bv.z); o.w = tanhf(s.w + bv.w);
        *reinterpret_cast<float4*>(&g_t2[(m0 + m) * 2048 + n0 + n]) = o;
    }
}

// ---------------- layer 2: h2 partials = t2 @ wn2^T (K-split x2) ----------------
__global__ void __launch_bounds__(256) layer2_kernel(int f) {
    __shared__ float ts[16][68];
    int tid = threadIdx.x;
    int o = tid & 63;
    int bq = tid >> 6;
    int bbase = blockIdx.x * 16;
    int kbase = blockIdx.y * 1024;
    const float* wn2K = g_wn2K[f];
    float acc[4] = {};
    for (int k0 = kbase; k0 < kbase + 1024; k0 += 64) {
        {
            int rr = tid >> 4, cq = tid & 15;
            float4 v = *reinterpret_cast<const float4*>(&g_t2[(bbase + rr) * 2048 + k0 + cq * 4]);
            *reinterpret_cast<float4*>(&ts[rr][cq * 4]) = v;
        }
        __syncthreads();
        #pragma unroll
        for (int kq = 0; kq < 16; kq++) {
            float4 w = *reinterpret_cast<const float4*>(&wn2K[o * 2048 + k0 + kq * 4]);
            #pragma unroll
            for (int j = 0; j < 4; j++) {
                float4 t = *reinterpret_cast<const float4*>(&ts[bq * 4 + j][kq * 4]);
                acc[j] = fmaf(w.x, t.x, acc[j]);
                acc[j] = fmaf(w.y, t.y, acc[j]);
                acc[j] = fmaf(w.z, t.z, acc[j]);
                acc[j] = fmaf(w.w, t.w, acc[j]);
            }
        }
        __syncthreads();
    }
    #pragma unroll
    for (int j = 0; j < 4; j++)
        g_h2[blockIdx.y * 65536 + (bbase + bq * 4 + j) * 64 + o] = acc[j];
}

// ---------------- Jacobian chain + gate + flip ----------------
__global__ void __launch_bounds__(256) jac_kernel(const float* __restrict__ xext,
                                                  int xsel, int nsel, int f,
                                                  const float* __restrict__ gate,
                                                  int hasGate, int accum,
                                                  const float* __restrict__ b2) {
    __shared__ float eg1s[1024];
    __shared__ float eg0s[32];
    __shared__ float eg2s[32];
    int d = blockIdx.x;
    int lane = threadIdx.x & 31, w = threadIdx.x >> 5;
    for (int i = threadIdx.x; i < 1024; i += 256) eg1s[i] = g_eg1[f][d * 1024 + i];
    if (threadIdx.x < 32) {
        eg0s[threadIdx.x] = g_eg0[f][d * 32 + threadIdx.x];
        eg2s[threadIdx.x] = g_eg2[f][d * 32 + threadIdx.x];
    }
    __syncthreads();
    const float* xcur = (xsel == 0) ? xext : ((xsel == 1) ? (const float*)g_xA : (const float*)g_xB);
    float* xnext = (nsel == 1) ? g_xA : g_xB;
    float gt = 0.f;
    if (hasGate) gt = *gate;
    float bias_d = b2[d];

    for (int bi = 0; bi < 16; bi++) {
        int b = blockIdx.y * 128 + bi * 8 + w;
        float t1v = g_t1[b * 2048 + d * 32 + lane];
        float v0 = eg0s[lane] * (1.f - t1v * t1v);
        float acc = 0.f;
        #pragma unroll
        for (int k = 0; k < 32; k++)
            acc = fmaf(eg1s[k * 32 + lane], __shfl_sync(WARP_FULL, v0, k), acc);
        float t2v = g_t2[b * 2048 + d * 32 + lane];
        float term = eg2s[lane] * acc * (1.f - t2v * t2v);
        #pragma unroll
        for (int off = 16; off; off >>= 1) term += __shfl_xor_sync(WARP_FULL, term, off);

        if (lane == 0) {
            float g = logf(term);
            float outv = g_h2[b * 64 + d] + g_h2[65536 + b * 64 + d] + bias_d;
            float l;
            if (hasGate) {
                float z = g + gt;
                float sp1 = (z  > 20.f) ? z  : log1pf(expf(z));
                float sp0 = (gt > 20.f) ? gt : log1pf(expf(gt));
                l = sp1 - sp0;
                float sgm = 1.f / (1.f + expf(-gt));
                xnext[b * 64 + (63 - d)] = sgm * outv + (1.f - sgm) * xcur[b * 64 + d];
            } else {
                l = g;
                xnext[b * 64 + d] = outv;
            }
            if (accum) g_lterm[b * 64 + d] += l;
            else       g_lterm[b * 64 + d]  = l;
        }
    }
}

// ---------------- final reduction ----------------
__global__ void __launch_bounds__(256) final_kernel(int xsel, float* __restrict__ out) {
    const float* xf = (xsel == 1) ? (const float*)g_xA : (const float*)g_xB;
    int b = blockIdx.x * 8 + (threadIdx.x >> 5);
    int lane = threadIdx.x & 31;
    float v1 = xf[b * 64 + lane];
    float v2 = xf[b * 64 + 32 + lane];
    float s = -0.5f * (v1 * v1 + v2 * v2)
              + g_lterm[b * 64 + lane] + g_lterm[b * 64 + 32 + lane];
    #pragma unroll
    for (int off = 16; off; off >>= 1) s += __shfl_xor_sync(WARP_FULL, s, off);
    if (lane == 0) out[b] = s - 32.f * 1.8378770664093453f;
}

// ---------------- launch ----------------
extern "C" void kernel_launch(void* const* d_in, const int* in_sizes, int n_in,
                              void* d_out, int out_size) {
    (void)in_sizes; (void)n_in; (void)out_size;
    const float* x     = (const float*)d_in[0];
    const float* gate0 = (const float*)d_in[28];
    const float* gate1 = (const float*)d_in[29];

    PrepPtrs P;
    for (int f = 0; f < 3; f++)
        for (int l = 0; l < 3; l++) {
            P.W [f * 3 + l] = (const float*)d_in[1 + f * 9 + l * 3 + 0];
            P.dw[f * 3 + l] = (const float*)d_in[1 + f * 9 + l * 3 + 1];
        }
    prep_all_kernel<<<dim3(520, 3), 256>>>(P);

    int xsel = 0;
    for (int f = 0; f < 3; f++) {
        const float* b0 = (const float*)d_in[1 + f * 9 + 2];
        const float* b1 = (const float*)d_in[1 + f * 9 + 5];
        const float* b2 = (const float*)d_in[1 + f * 9 + 8];

        layer0_kernel<<<dim3(8, 128), 256>>>(x, xsel, f, b0);
        layer1_kernel<<<dim3(32, 8, 8), 256>>>(f);
        reduce1_kernel<<<dim3(32, 8), 256>>>(b1);
        layer2_kernel<<<dim3(64, 2), 256>>>(f);

        const float* gate = (f == 0) ? gate0 : ((f == 1) ? gate1 : nullptr);
        int nsel = (f & 1) ? 2 : 1;
        jac_kernel<<<dim3(64, 8), 256>>>(x, xsel, nsel, f, gate, (f < 2) ? 1 : 0, (f > 0) ? 1 : 0, b2);
        xsel = nsel;
    }
    final_kernel<<<128, 256>>>(xsel, (float*)d_out);
}

// round 6
// speedup vs baseline: 3.6901x; 1.2831x over previous
#include <cuda_runtime.h>
#include <cuda_bf16.h>
#include <math.h>
#include <stdint.h>

#define WARP_FULL 0xFFFFFFFFu

// ---------------- scratch (device globals; no allocation) ----------------
__device__ float    g_wn0T[3][64 * 2048];
__device__ uint32_t g_wn1p[3][2048 * 2048];   // [f][n][k] packed (bf16 hi | lo<<16)
__device__ float    g_wn2K[3][64 * 2048];
__device__ float    g_eg0 [3][2048];
__device__ float    g_eg1 [3][64 * 32 * 32];
__device__ float    g_eg2 [3][64 * 32];
__device__ float    g_t1 [1024 * 2048];
__device__ uint32_t g_t1p[1024 * 2048];       // packed split-bf16 of t1
__device__ float    g_t2 [1024 * 2048];
__device__ float    g_part[32 * 4 * 8 * 8192];  // [(nt*4+ch)*8+mt][m 128][n 64]
__device__ float    g_h2 [2 * 1024 * 64];
__device__ float    g_xA [1024 * 64];
__device__ float    g_xB [1024 * 64];
__device__ float    g_lterm[1024 * 64];

struct PrepPtrs { const float* W[9]; const float* dw[9]; };

__device__ __forceinline__ uint32_t pack_split(float v) {
    __nv_bfloat16 h = __float2bfloat16(v);
    __nv_bfloat16 l = __float2bfloat16(v - __bfloat162float(h));
    uint16_t hb = *reinterpret_cast<uint16_t*>(&h);
    uint16_t lb = *reinterpret_cast<uint16_t*>(&l);
    return (uint32_t)hb | ((uint32_t)lb << 16);
}

__device__ __forceinline__ void mma16816(float* c, const uint32_t* a, const uint32_t* b) {
    asm volatile("mma.sync.aligned.m16n8k16.row.col.f32.bf16.bf16.f32 "
        "{%0,%1,%2,%3}, {%4,%5,%6,%7}, {%8,%9}, {%0,%1,%2,%3};"
        : "+f"(c[0]), "+f"(c[1]), "+f"(c[2]), "+f"(c[3])
        : "r"(a[0]), "r"(a[1]), "r"(a[2]), "r"(a[3]), "r"(b[0]), "r"(b[1]));
}

// ---------------- merged weight preprocessing: warp per row ----------------
__global__ void __launch_bounds__(256) prep_all_kernel(PrepPtrs P) {
    int f = blockIdx.y;
    int wr = blockIdx.x * 8 + (threadIdx.x >> 5);
    int lane = threadIdx.x & 31;

    if (wr < 2048) {                        // ---- layer0
        const float* W  = P.W [f * 3 + 0];
        const float* dw = P.dw[f * 3 + 0];
        int r = wr, blk = r >> 5;
        float vals[2]; float s = 0.f;
        #pragma unroll
        for (int i = 0; i < 2; i++) {
            int c = lane + 32 * i;
            float raw = W[r * 64 + c];
            float v = (c < blk) ? raw : ((c == blk) ? expf(raw) : 0.f);
            vals[i] = v; s += v * v;
        }
        #pragma unroll
        for (int off = 16; off; off >>= 1) s += __shfl_xor_sync(WARP_FULL, s, off);
        float scale = expf(dw[r]) * rsqrtf(s);
        #pragma unroll
        for (int i = 0; i < 2; i++) {
            int c = lane + 32 * i;
            float wv = vals[i] * scale;
            g_wn0T[f][c * 2048 + r] = wv;
            if (c == blk) g_eg0[f][r] = wv;
        }
    } else if (wr < 4096) {                 // ---- layer1 (packed split bf16)
        const float* W  = P.W [f * 3 + 1];
        const float* dw = P.dw[f * 3 + 1];
        int r = wr - 2048, blk = r >> 5;
        int d0 = blk * 32, d1 = d0 + 32;
        int cmax = ((r >> 6) + 1) << 6;
        float s = 0.f;
        for (int c = lane; c < d1; c += 32) {
            float wv = W[r * 2048 + c];
            if (c >= d0) wv = expf(wv);
            s += wv * wv;
        }
        #pragma unroll
        for (int off = 16; off; off >>= 1) s += __shfl_xor_sync(WARP_FULL, s, off);
        float scale = expf(dw[r]) * rsqrtf(s);
        for (int c = lane; c < cmax; c += 32) {
            float o;
            if (c < d0)       o = W[r * 2048 + c] * scale;
            else if (c < d1) {
                o = expf(W[r * 2048 + c]) * scale;
                g_eg1[f][blk * 1024 + (c - d0) * 32 + (r & 31)] = o;
            } else            o = 0.f;
            g_wn1p[f][r * 2048 + c] = pack_split(o);
        }
    } else {                                // ---- layer2
        const float* W  = P.W [f * 3 + 2];
        const float* dw = P.dw[f * 3 + 2];
        int r = wr - 4096;
        int d0 = r * 32, d1 = d0 + 32;
        float s = 0.f;
        for (int c = lane; c < d1; c += 32) {
            float wv = W[r * 2048 + c];
            if (c >= d0) wv = expf(wv);
            s += wv * wv;
        }
        #pragma unroll
        for (int off = 16; off; off >>= 1) s += __shfl_xor_sync(WARP_FULL, s, off);
        float scale = expf(dw[r]) * rsqrtf(s);
        for (int c = lane; c < 2048; c += 32) {
            float o;
            if (c < d0)       o = W[r * 2048 + c] * scale;
            else if (c < d1) {
                o = expf(W[r * 2048 + c]) * scale;
                g_eg2[f][r * 32 + (c - d0)] = o;
            } else            o = 0.f;
            g_wn2K[f][r * 2048 + c] = o;
        }
    }
}

// ---------------- layer 0: t1 = tanh(x @ wn0^T + b0) + packed split ----------------
__global__ void __launch_bounds__(256) layer0_kernel(const float* __restrict__ xext,
                                                     int xsel, int f,
                                                     const float* __restrict__ bias) {
    __shared__ float xs[64][8];
    const float* xsrc = (xsel == 0) ? xext : ((xsel == 1) ? (const float*)g_xA : (const float*)g_xB);
    int o = blockIdx.x * 256 + threadIdx.x;
    int bbase = blockIdx.y * 8;
    for (int i = threadIdx.x; i < 512; i += 256) {
        int k = i >> 3, bi = i & 7;
        xs[k][bi] = xsrc[(bbase + bi) * 64 + k];
    }
    __syncthreads();
    const float* wn0T = g_wn0T[f];
    float bv = bias[o];
    float acc[8];
    #pragma unroll
    for (int bi = 0; bi < 8; bi++) acc[bi] = bv;
    #pragma unroll 16
    for (int k = 0; k < 64; k++) {
        float w = wn0T[k * 2048 + o];
        float4 x0 = *reinterpret_cast<const float4*>(&xs[k][0]);
        float4 x1 = *reinterpret_cast<const float4*>(&xs[k][4]);
        acc[0] = fmaf(x0.x, w, acc[0]); acc[1] = fmaf(x0.y, w, acc[1]);
        acc[2] = fmaf(x0.z, w, acc[2]); acc[3] = fmaf(x0.w, w, acc[3]);
        acc[4] = fmaf(x1.x, w, acc[4]); acc[5] = fmaf(x1.y, w, acc[5]);
        acc[6] = fmaf(x1.z, w, acc[6]); acc[7] = fmaf(x1.w, w, acc[7]);
    }
    #pragma unroll
    for (int bi = 0; bi < 8; bi++) {
        float t = tanhf(acc[bi]);
        int idx = (bbase + bi) * 2048 + o;
        g_t1[idx] = t;
        g_t1p[idx] = pack_split(t);
    }
}

// ---------------- layer 1: split-bf16 HMMA GEMM -> fp32 partials ----------------
// grid (32 nt, 8 mt, 4 ch), 256 threads (8 warps). BM=128, BN=64, BK=32.
// Warp w: m-quarter (w&3)*32, n-half (w>>2)*32. Atoms: 2(m16) x 4(n8).
#define L1_AS_STRIDE 40
#define L1_AS_WORDS  (128 * L1_AS_STRIDE)   // 5120
#define L1_BS_WORDS  (64 * L1_AS_STRIDE)    // 2560
#define L1_SMEM_BYTES ((2 * L1_AS_WORDS + 2 * L1_BS_WORDS) * 4)  // 61440

__global__ void __launch_bounds__(256) layer1_mma_kernel(int f) {
    const int nt = blockIdx.x, mt = blockIdx.y, ch = blockIdx.z;
    const int Klim = (nt + 1) * 64;
    const int kbeg = ch * 512;
    if (kbeg >= Klim) return;
    const int kend = min(kbeg + 512, Klim);
    const int m0 = mt * 128, n0 = nt * 64;

    extern __shared__ uint32_t sm[];
    uint32_t* As[2] = { sm, sm + L1_AS_WORDS };
    uint32_t* Bs[2] = { sm + 2 * L1_AS_WORDS, sm + 2 * L1_AS_WORDS + L1_BS_WORDS };

    const int tid = threadIdx.x;
    const int w = tid >> 5, l = tid & 31;
    const int mw = (w & 3) * 32, nw = (w >> 2) * 32;
    const int lr = l >> 2, lc2 = (l & 3) * 2;

    const uint32_t* t1p = g_t1p;
    const uint32_t* w1p = g_wn1p[f];

    float acc[2][4][4] = {};

    // loader indices: u = tid + 256*i ; row = u>>3, q = u&7 (uint4 of 4 words)
    const int lrow = tid >> 3, lq = (tid & 7) * 4;

    int buf = 0;
    // preload first tile
    {
        int kc = kbeg;
        #pragma unroll
        for (int i = 0; i < 4; i++) {
            int row = lrow + i * 32;
            uint4 v = *reinterpret_cast<const uint4*>(&t1p[(m0 + row) * 2048 + kc + lq]);
            *reinterpret_cast<uint4*>(&As[0][row * L1_AS_STRIDE + lq]) = v;
        }
        #pragma unroll
        for (int i = 0; i < 2; i++) {
            int row = lrow + i * 32;
            uint4 v = *reinterpret_cast<const uint4*>(&w1p[(n0 + row) * 2048 + kc + lq]);
            *reinterpret_cast<uint4*>(&Bs[0][row * L1_AS_STRIDE + lq]) = v;
        }
    }
    __syncthreads();

    for (int kc = kbeg; kc < kend; kc += 32) {
        // prefetch next tile into regs
        uint4 pa[4], pb[2];
        bool more = (kc + 32) < kend;
        if (more) {
            #pragma unroll
            for (int i = 0; i < 4; i++)
                pa[i] = *reinterpret_cast<const uint4*>(&t1p[(m0 + lrow + i * 32) * 2048 + kc + 32 + lq]);
            #pragma unroll
            for (int i = 0; i < 2; i++)
                pb[i] = *reinterpret_cast<const uint4*>(&w1p[(n0 + lrow + i * 32) * 2048 + kc + 32 + lq]);
        }

        const uint32_t* A = As[buf];
        const uint32_t* B = Bs[buf];
        #pragma unroll
        for (int kk = 0; kk < 32; kk += 16) {
            uint32_t ah[2][4], al[2][4], bh[4][2], bl[4][2];
            #pragma unroll
            for (int i = 0; i < 2; i++) {
                int rbase = mw + i * 16 + lr;
                #pragma unroll
                for (int h = 0; h < 2; h++) {       // m-half (rows +0/+8)
                    #pragma unroll
                    for (int kq = 0; kq < 2; kq++) { // k-half (cols +0/+8)
                        uint2 v = *reinterpret_cast<const uint2*>(
                            &A[(rbase + h * 8) * L1_AS_STRIDE + kk + lc2 + kq * 8]);
                        int ri = h + kq * 2;        // a0,a1,a2,a3 ordering
                        ah[i][ri] = __byte_perm(v.x, v.y, 0x5410);
                        al[i][ri] = __byte_perm(v.x, v.y, 0x7632);
                    }
                }
            }
            #pragma unroll
            for (int j = 0; j < 4; j++) {
                int nrow = nw + j * 8 + lr;
                #pragma unroll
                for (int kq = 0; kq < 2; kq++) {
                    uint2 v = *reinterpret_cast<const uint2*>(
                        &B[nrow * L1_AS_STRIDE + kk + lc2 + kq * 8]);
                    bh[j][kq] = __byte_perm(v.x, v.y, 0x5410);
                    bl[j][kq] = __byte_perm(v.x, v.y, 0x7632);
                }
            }
            #pragma unroll
            for (int i = 0; i < 2; i++)
                #pragma unroll
                for (int j = 0; j < 4; j++) {
                    mma16816(acc[i][j], ah[i], bh[j]);
                    mma16816(acc[i][j], ah[i], bl[j]);
                    mma16816(acc[i][j], al[i], bh[j]);
                }
        }
        __syncthreads();
        if (more) {
            int nb = buf ^ 1;
            #pragma unroll
            for (int i = 0; i < 4; i++)
                *reinterpret_cast<uint4*>(&As[nb][(lrow + i * 32) * L1_AS_STRIDE + lq]) = pa[i];
            #pragma unroll
            for (int i = 0; i < 2; i++)
                *reinterpret_cast<uint4*>(&Bs[nb][(lrow + i * 32) * L1_AS_STRIDE + lq]) = pb[i];
            __syncthreads();
        }
        buf ^= 1;
    }

    float* out = &g_part[(size_t)((nt * 4 + ch) * 8 + mt) * 8192];
    #pragma unroll
    for (int i = 0; i < 2; i++) {
        int r = mw + i * 16 + lr;
        #pragma unroll
        for (int j = 0; j < 4; j++) {
            int n = nw + j * 8 + lc2;
            *reinterpret_cast<float2*>(&out[r * 64 + n])       = make_float2(acc[i][j][0], acc[i][j][1]);
            *reinterpret_cast<float2*>(&out[(r + 8) * 64 + n]) = make_float2(acc[i][j][2], acc[i][j][3]);
        }
    }
}

// ---------------- layer1 reduce: t2 = tanh(sum partials + b1) ----------------
__global__ void __launch_bounds__(256) reduce1_kernel(const float* __restrict__ bias) {
    const int nt = blockIdx.x, ms = blockIdx.y;
    const int mt = ms >> 2, sub = ms & 3;
    const int Cnt = (nt + 8) >> 3;
    const int n0 = nt * 64;
    const float* base = &g_part[(size_t)((nt * 4) * 8 + mt) * 8192 + sub * 2048];
    const int row0 = mt * 128 + sub * 32;
    for (int e = threadIdx.x * 4; e < 2048; e += 1024) {
        float4 s = *reinterpret_cast<const float4*>(&base[e]);
        for (int c = 1; c < Cnt; c++) {
            float4 p = *reinterpret_cast<const float4*>(&base[(size_t)c * 65536 + e]);
            s.x += p.x; s.y += p.y; s.z += p.z; s.w += p.w;
        }
        int m = e >> 6, n = e & 63;
        float4 bv = *reinterpret_cast<const float4*>(&bias[n0 + n]);
        float4 o;
        o.x = tanhf(s.x + bv.x); o.y = tanhf(s.y + bv.y);
        o.z = tanhf(s.z + bv.z); o.w = tanhf(s.w + bv.w);
        *reinterpret_cast<float4*>(&g_t2[(row0 + m) * 2048 + n0 + n]) = o;
    }
}

// ---------------- layer 2: h2 partials = t2 @ wn2^T (K-split x2) ----------------
__global__ void __launch_bounds__(256) layer2_kernel(int f) {
    __shared__ float ts[16][68];
    int tid = threadIdx.x;
    int o = tid & 63;
    int bq = tid >> 6;
    int bbase = blockIdx.x * 16;
    int kbase = blockIdx.y * 1024;
    const float* wn2K = g_wn2K[f];
    float acc[4] = {};
    for (int k0 = kbase; k0 < kbase + 1024; k0 += 64) {
        {
            int rr = tid >> 4, cq = tid & 15;
            float4 v = *reinterpret_cast<const float4*>(&g_t2[(bbase + rr) * 2048 + k0 + cq * 4]);
            *reinterpret_cast<float4*>(&ts[rr][cq * 4]) = v;
        }
        __syncthreads();
        #pragma unroll
        for (int kq = 0; kq < 16; kq++) {
            float4 w = *reinterpret_cast<const float4*>(&wn2K[o * 2048 + k0 + kq * 4]);
            #pragma unroll
            for (int j = 0; j < 4; j++) {
                float4 t = *reinterpret_cast<const float4*>(&ts[bq * 4 + j][kq * 4]);
                acc[j] = fmaf(w.x, t.x, acc[j]);
                acc[j] = fmaf(w.y, t.y, acc[j]);
                acc[j] = fmaf(w.z, t.z, acc[j]);
                acc[j] = fmaf(w.w, t.w, acc[j]);
            }
        }
        __syncthreads();
    }
    #pragma unroll
    for (int j = 0; j < 4; j++)
        g_h2[blockIdx.y * 65536 + (bbase + bq * 4 + j) * 64 + o] = acc[j];
}

// ---------------- Jacobian chain + gate + flip ----------------
__global__ void __launch_bounds__(256) jac_kernel(const float* __restrict__ xext,
                                                  int xsel, int nsel, int f,
                                                  const float* __restrict__ gate,
                                                  int hasGate, int accum,
                                                  const float* __restrict__ b2) {
    __shared__ float eg1s[1024];
    __shared__ float eg0s[32];
    __shared__ float eg2s[32];
    int d = blockIdx.x;
    int lane = threadIdx.x & 31, w = threadIdx.x >> 5;
    for (int i = threadIdx.x; i < 1024; i += 256) eg1s[i] = g_eg1[f][d * 1024 + i];
    if (threadIdx.x < 32) {
        eg0s[threadIdx.x] = g_eg0[f][d * 32 + threadIdx.x];
        eg2s[threadIdx.x] = g_eg2[f][d * 32 + threadIdx.x];
    }
    __syncthreads();
    const float* xcur = (xsel == 0) ? xext : ((xsel == 1) ? (const float*)g_xA : (const float*)g_xB);
    float* xnext = (nsel == 1) ? g_xA : g_xB;
    float gt = 0.f;
    if (hasGate) gt = *gate;
    float bias_d = b2[d];

    for (int bi = 0; bi < 16; bi++) {
        int b = blockIdx.y * 128 + bi * 8 + w;
        float t1v = g_t1[b * 2048 + d * 32 + lane];
        float v0 = eg0s[lane] * (1.f - t1v * t1v);
        float acc = 0.f;
        #pragma unroll
        for (int k = 0; k < 32; k++)
            acc = fmaf(eg1s[k * 32 + lane], __shfl_sync(WARP_FULL, v0, k), acc);
        float t2v = g_t2[b * 2048 + d * 32 + lane];
        float term = eg2s[lane] * acc * (1.f - t2v * t2v);
        #pragma unroll
        for (int off = 16; off; off >>= 1) term += __shfl_xor_sync(WARP_FULL, term, off);

        if (lane == 0) {
            float g = logf(term);
            float outv = g_h2[b * 64 + d] + g_h2[65536 + b * 64 + d] + bias_d;
            float l;
            if (hasGate) {
                float z = g + gt;
                float sp1 = (z  > 20.f) ? z  : log1pf(expf(z));
                float sp0 = (gt > 20.f) ? gt : log1pf(expf(gt));
                l = sp1 - sp0;
                float sgm = 1.f / (1.f + expf(-gt));
                xnext[b * 64 + (63 - d)] = sgm * outv + (1.f - sgm) * xcur[b * 64 + d];
            } else {
                l = g;
                xnext[b * 64 + d] = outv;
            }
            if (accum) g_lterm[b * 64 + d] += l;
            else       g_lterm[b * 64 + d]  = l;
        }
    }
}

// ---------------- final reduction ----------------
__global__ void __launch_bounds__(256) final_kernel(int xsel, float* __restrict__ out) {
    const float* xf = (xsel == 1) ? (const float*)g_xA : (const float*)g_xB;
    int b = blockIdx.x * 8 + (threadIdx.x >> 5);
    int lane = threadIdx.x & 31;
    float v1 = xf[b * 64 + lane];
    float v2 = xf[b * 64 + 32 + lane];
    float s = -0.5f * (v1 * v1 + v2 * v2)
              + g_lterm[b * 64 + lane] + g_lterm[b * 64 + 32 + lane];
    #pragma unroll
    for (int off = 16; off; off >>= 1) s += __shfl_xor_sync(WARP_FULL, s, off);
    if (lane == 0) out[b] = s - 32.f * 1.8378770664093453f;
}

// ---------------- launch ----------------
extern "C" void kernel_launch(void* const* d_in, const int* in_sizes, int n_in,
                              void* d_out, int out_size) {
    (void)in_sizes; (void)n_in; (void)out_size;
    const float* x     = (const float*)d_in[0];
    const float* gate0 = (const float*)d_in[28];
    const float* gate1 = (const float*)d_in[29];

    static int smem_set = 0;
    if (!smem_set) {
        cudaFuncSetAttribute(layer1_mma_kernel,
                             cudaFuncAttributeMaxDynamicSharedMemorySize, L1_SMEM_BYTES);
        smem_set = 1;
    }

    PrepPtrs P;
    for (int f = 0; f < 3; f++)
        for (int l = 0; l < 3; l++) {
            P.W [f * 3 + l] = (const float*)d_in[1 + f * 9 + l * 3 + 0];
            P.dw[f * 3 + l] = (const float*)d_in[1 + f * 9 + l * 3 + 1];
        }
    prep_all_kernel<<<dim3(520, 3), 256>>>(P);

    int xsel = 0;
    for (int f = 0; f < 3; f++) {
        const float* b0 = (const float*)d_in[1 + f * 9 + 2];
        const float* b1 = (const float*)d_in[1 + f * 9 + 5];
        const float* b2 = (const float*)d_in[1 + f * 9 + 8];

        layer0_kernel<<<dim3(8, 128), 256>>>(x, xsel, f, b0);
        layer1_mma_kernel<<<dim3(32, 8, 4), 256, L1_SMEM_BYTES>>>(f);
        reduce1_kernel<<<dim3(32, 32), 256>>>(b1);
        layer2_kernel<<<dim3(64, 2), 256>>>(f);

        const float* gate = (f == 0) ? gate0 : ((f == 1) ? gate1 : nullptr);
        int nsel = (f & 1) ? 2 : 1;
        jac_kernel<<<dim3(64, 8), 256>>>(x, xsel, nsel, f, gate, (f < 2) ? 1 : 0, (f > 0) ? 1 : 0, b2);
        xsel = nsel;
    }
    final_kernel<<<128, 256>>>(xsel, (float*)d_out);
}

// round 7
// speedup vs baseline: 3.6907x; 1.0002x over previous
#include <cuda_runtime.h>
#include <cuda_bf16.h>
#include <math.h>
#include <stdint.h>

#define WARP_FULL 0xFFFFFFFFu

// ---------------- scratch (device globals; no allocation) ----------------
__device__ float         g_wn0T[3][64 * 2048];
__device__ __nv_bfloat16 g_wn1h[3][2048 * 2048];   // [f][n][k] hi plane
__device__ __nv_bfloat16 g_wn1l[3][2048 * 2048];   // [f][n][k] lo plane
__device__ float         g_wn2K[3][64 * 2048];
__device__ float         g_eg0 [3][2048];
__device__ float         g_eg1 [3][64 * 32 * 32];
__device__ float         g_eg2 [3][64 * 32];
__device__ __nv_bfloat16 g_t1h[1024 * 2048];
__device__ __nv_bfloat16 g_t1l[1024 * 2048];
__device__ float         g_t2 [1024 * 2048];
__device__ float         g_part[32 * 4 * 8 * 8192];  // [(nt*4+ch)*8+mt][m 128][n 64]
__device__ float         g_h2 [2 * 1024 * 64];
__device__ float         g_xA [1024 * 64];
__device__ float         g_xB [1024 * 64];
__device__ float         g_lterm[1024 * 64];

struct PrepPtrs { const float* W[9]; const float* dw[9]; };

__device__ __forceinline__ void mma16816(float* c, const uint32_t* a, const uint32_t* b) {
    asm volatile("mma.sync.aligned.m16n8k16.row.col.f32.bf16.bf16.f32 "
        "{%0,%1,%2,%3}, {%4,%5,%6,%7}, {%8,%9}, {%0,%1,%2,%3};"
        : "+f"(c[0]), "+f"(c[1]), "+f"(c[2]), "+f"(c[3])
        : "r"(a[0]), "r"(a[1]), "r"(a[2]), "r"(a[3]), "r"(b[0]), "r"(b[1]));
}
__device__ __forceinline__ uint32_t smem_u32(const void* p) {
    uint32_t a;
    asm("{ .reg .u64 t; cvta.to.shared.u64 t, %1; cvt.u32.u64 %0, t; }" : "=r"(a) : "l"(p));
    return a;
}
__device__ __forceinline__ void cp16(uint32_t dst, const void* src) {
    asm volatile("cp.async.cg.shared.global [%0], [%1], 16;" :: "r"(dst), "l"(src));
}
#define CP_COMMIT() asm volatile("cp.async.commit_group;" ::: "memory")
#define CP_WAIT(n)  asm volatile("cp.async.wait_group %0;" :: "n"(n) : "memory")

// ---------------- merged weight preprocessing: warp per row ----------------
__global__ void __launch_bounds__(256) prep_all_kernel(PrepPtrs P) {
    int f = blockIdx.y;
    int wr = blockIdx.x * 8 + (threadIdx.x >> 5);
    int lane = threadIdx.x & 31;

    if (wr < 2048) {                        // ---- layer0
        const float* W  = P.W [f * 3 + 0];
        const float* dw = P.dw[f * 3 + 0];
        int r = wr, blk = r >> 5;
        float vals[2]; float s = 0.f;
        #pragma unroll
        for (int i = 0; i < 2; i++) {
            int c = lane + 32 * i;
            float raw = W[r * 64 + c];
            float v = (c < blk) ? raw : ((c == blk) ? expf(raw) : 0.f);
            vals[i] = v; s += v * v;
        }
        #pragma unroll
        for (int off = 16; off; off >>= 1) s += __shfl_xor_sync(WARP_FULL, s, off);
        float scale = expf(dw[r]) * rsqrtf(s);
        #pragma unroll
        for (int i = 0; i < 2; i++) {
            int c = lane + 32 * i;
            float wv = vals[i] * scale;
            g_wn0T[f][c * 2048 + r] = wv;
            if (c == blk) g_eg0[f][r] = wv;
        }
    } else if (wr < 4096) {                 // ---- layer1 (split bf16 planes)
        const float* W  = P.W [f * 3 + 1];
        const float* dw = P.dw[f * 3 + 1];
        int r = wr - 2048, blk = r >> 5;
        int d0 = blk * 32, d1 = d0 + 32;
        int cmax = ((r >> 6) + 1) << 6;
        float s = 0.f;
        for (int c = lane; c < d1; c += 32) {
            float wv = W[r * 2048 + c];
            if (c >= d0) wv = expf(wv);
            s += wv * wv;
        }
        #pragma unroll
        for (int off = 16; off; off >>= 1) s += __shfl_xor_sync(WARP_FULL, s, off);
        float scale = expf(dw[r]) * rsqrtf(s);
        for (int c = lane; c < cmax; c += 32) {
            float o;
            if (c < d0)       o = W[r * 2048 + c] * scale;
            else if (c < d1) {
                o = expf(W[r * 2048 + c]) * scale;
                g_eg1[f][blk * 1024 + (c - d0) * 32 + (r & 31)] = o;
            } else            o = 0.f;
            __nv_bfloat16 oh = __float2bfloat16(o);
            g_wn1h[f][r * 2048 + c] = oh;
            g_wn1l[f][r * 2048 + c] = __float2bfloat16(o - __bfloat162float(oh));
        }
    } else {                                // ---- layer2
        const float* W  = P.W [f * 3 + 2];
        const float* dw = P.dw[f * 3 + 2];
        int r = wr - 4096;
        int d0 = r * 32, d1 = d0 + 32;
        float s = 0.f;
        for (int c = lane; c < d1; c += 32) {
            float wv = W[r * 2048 + c];
            if (c >= d0) wv = expf(wv);
            s += wv * wv;
        }
        #pragma unroll
        for (int off = 16; off; off >>= 1) s += __shfl_xor_sync(WARP_FULL, s, off);
        float scale = expf(dw[r]) * rsqrtf(s);
        for (int c = lane; c < 2048; c += 32) {
            float o;
            if (c < d0)       o = W[r * 2048 + c] * scale;
            else if (c < d1) {
                o = expf(W[r * 2048 + c]) * scale;
                g_eg2[f][r * 32 + (c - d0)] = o;
            } else            o = 0.f;
            g_wn2K[f][r * 2048 + c] = o;
        }
    }
}

// ---------------- layer 0: t1 = tanh(x @ wn0^T + b0) -> split bf16 planes ----------------
__global__ void __launch_bounds__(256) layer0_kernel(const float* __restrict__ xext,
                                                     int xsel, int f,
                                                     const float* __restrict__ bias) {
    __shared__ float xs[64][8];
    const float* xsrc = (xsel == 0) ? xext : ((xsel == 1) ? (const float*)g_xA : (const float*)g_xB);
    int o = blockIdx.x * 256 + threadIdx.x;
    int bbase = blockIdx.y * 8;
    for (int i = threadIdx.x; i < 512; i += 256) {
        int k = i >> 3, bi = i & 7;
        xs[k][bi] = xsrc[(bbase + bi) * 64 + k];
    }
    __syncthreads();
    const float* wn0T = g_wn0T[f];
    float bv = bias[o];
    float acc[8];
    #pragma unroll
    for (int bi = 0; bi < 8; bi++) acc[bi] = bv;
    #pragma unroll 16
    for (int k = 0; k < 64; k++) {
        float w = wn0T[k * 2048 + o];
        float4 x0 = *reinterpret_cast<const float4*>(&xs[k][0]);
        float4 x1 = *reinterpret_cast<const float4*>(&xs[k][4]);
        acc[0] = fmaf(x0.x, w, acc[0]); acc[1] = fmaf(x0.y, w, acc[1]);
        acc[2] = fmaf(x0.z, w, acc[2]); acc[3] = fmaf(x0.w, w, acc[3]);
        acc[4] = fmaf(x1.x, w, acc[4]); acc[5] = fmaf(x1.y, w, acc[5]);
        acc[6] = fmaf(x1.z, w, acc[6]); acc[7] = fmaf(x1.w, w, acc[7]);
    }
    #pragma unroll
    for (int bi = 0; bi < 8; bi++) {
        float t = tanhf(acc[bi]);
        int idx = (bbase + bi) * 2048 + o;
        __nv_bfloat16 th = __float2bfloat16(t);
        g_t1h[idx] = th;
        g_t1l[idx] = __float2bfloat16(t - __bfloat162float(th));
    }
}

// ---------------- layer 1: split-bf16 HMMA GEMM (plane layout, cp.async) ----------------
// grid (32 nt, 8 mt, 4 ch), 256 threads (8 warps). BM=128, BN=64, chunk=32.
// Smem rows have 40-bf16 stride (conflict-free LDS.32 fragments).
#define L1_AH 0
#define L1_AL (128 * 40)
#define L1_BH (256 * 40)
#define L1_BL (256 * 40 + 64 * 40)
#define L1_BUF (384 * 40)                  // 15360 bf16 per buffer
#define L1_SMEM_BYTES (2 * L1_BUF * 2)     // 61440 bytes

__global__ void __launch_bounds__(256) layer1_mma_kernel(int f) {
    const int nt = blockIdx.x, mt = blockIdx.y, ch = blockIdx.z;
    const int Klim = (nt + 1) * 64;
    const int kbeg = ch * 512;
    if (kbeg >= Klim) return;
    const int kend = min(kbeg + 512, Klim);
    const int m0 = mt * 128, n0 = nt * 64;

    extern __shared__ __nv_bfloat16 smb[];
    const uint32_t sb = smem_u32(smb);

    const int tid = threadIdx.x;
    const int w = tid >> 5, l = tid & 31;
    const int mw = (w & 3) * 32, nw = (w >> 2) * 32;
    const int lr = l >> 2, lc2 = (l & 3) * 2;

    const __nv_bfloat16* t1h = g_t1h;
    const __nv_bfloat16* t1l = g_t1l;
    const __nv_bfloat16* w1h = g_wn1h[f];
    const __nv_bfloat16* w1l = g_wn1l[f];

    // loader coords
    const int ra1 = tid >> 2,        qa1 = (tid & 3) * 8;          // A rows 0..63
    const int ra2 = (tid + 256) >> 2, qa2 = qa1;                   // A rows 64..127
    const int rb  = tid >> 2,        qb  = qa1;                    // B rows 0..63

    auto load_chunk = [&](uint32_t base, int kc) {
        cp16(base + (uint32_t)(L1_AH + ra1 * 40 + qa1) * 2, &t1h[(m0 + ra1) * 2048 + kc + qa1]);
        cp16(base + (uint32_t)(L1_AH + ra2 * 40 + qa2) * 2, &t1h[(m0 + ra2) * 2048 + kc + qa2]);
        cp16(base + (uint32_t)(L1_AL + ra1 * 40 + qa1) * 2, &t1l[(m0 + ra1) * 2048 + kc + qa1]);
        cp16(base + (uint32_t)(L1_AL + ra2 * 40 + qa2) * 2, &t1l[(m0 + ra2) * 2048 + kc + qa2]);
        cp16(base + (uint32_t)(L1_BH + rb  * 40 + qb ) * 2, &w1h[(n0 + rb) * 2048 + kc + qb]);
        cp16(base + (uint32_t)(L1_BL + rb  * 40 + qb ) * 2, &w1l[(n0 + rb) * 2048 + kc + qb]);
        CP_COMMIT();
    };

    float acc[2][4][4] = {};

    load_chunk(sb, kbeg);
    int buf = 0;
    for (int kc = kbeg; kc < kend; kc += 32) {
        bool more = (kc + 32) < kend;
        if (more) load_chunk(sb + (uint32_t)(buf ^ 1) * L1_BUF * 2, kc + 32);
        if (more) { CP_WAIT(1); } else { CP_WAIT(0); }
        __syncthreads();

        const __nv_bfloat16* B = smb + buf * L1_BUF;
        #pragma unroll
        for (int kk = 0; kk < 32; kk += 16) {
            uint32_t ah[2][4], al[2][4], bh[4][2], bl[4][2];
            #pragma unroll
            for (int i = 0; i < 2; i++) {
                int R = mw + i * 16 + lr;
                ah[i][0] = *(const uint32_t*)&B[L1_AH + R * 40 + kk + lc2];
                ah[i][1] = *(const uint32_t*)&B[L1_AH + (R + 8) * 40 + kk + lc2];
                ah[i][2] = *(const uint32_t*)&B[L1_AH + R * 40 + kk + 8 + lc2];
                ah[i][3] = *(const uint32_t*)&B[L1_AH + (R + 8) * 40 + kk + 8 + lc2];
                al[i][0] = *(const uint32_t*)&B[L1_AL + R * 40 + kk + lc2];
                al[i][1] = *(const uint32_t*)&B[L1_AL + (R + 8) * 40 + kk + lc2];
                al[i][2] = *(const uint32_t*)&B[L1_AL + R * 40 + kk + 8 + lc2];
                al[i][3] = *(const uint32_t*)&B[L1_AL + (R + 8) * 40 + kk + 8 + lc2];
            }
            #pragma unroll
            for (int j = 0; j < 4; j++) {
                int N = nw + j * 8 + lr;
                bh[j][0] = *(const uint32_t*)&B[L1_BH + N * 40 + kk + lc2];
                bh[j][1] = *(const uint32_t*)&B[L1_BH + N * 40 + kk + 8 + lc2];
                bl[j][0] = *(const uint32_t*)&B[L1_BL + N * 40 + kk + lc2];
                bl[j][1] = *(const uint32_t*)&B[L1_BL + N * 40 + kk + 8 + lc2];
            }
            #pragma unroll
            for (int i = 0; i < 2; i++)
                #pragma unroll
                for (int j = 0; j < 4; j++) {
                    mma16816(acc[i][j], ah[i], bh[j]);
                    mma16816(acc[i][j], ah[i], bl[j]);
                    mma16816(acc[i][j], al[i], bh[j]);
                }
        }
        __syncthreads();
        buf ^= 1;
    }

    float* out = &g_part[(size_t)((nt * 4 + ch) * 8 + mt) * 8192];
    #pragma unroll
    for (int i = 0; i < 2; i++) {
        int r = mw + i * 16 + lr;
        #pragma unroll
        for (int j = 0; j < 4; j++) {
            int n = nw + j * 8 + lc2;
            *reinterpret_cast<float2*>(&out[r * 64 + n])       = make_float2(acc[i][j][0], acc[i][j][1]);
            *reinterpret_cast<float2*>(&out[(r + 8) * 64 + n]) = make_float2(acc[i][j][2], acc[i][j][3]);
        }
    }
}

// ---------------- layer1 reduce: t2 = tanh(sum partials + b1) ----------------
__global__ void __launch_bounds__(256) reduce1_kernel(const float* __restrict__ bias) {
    const int nt = blockIdx.x, ms = blockIdx.y;
    const int mt = ms >> 2, sub = ms & 3;
    const int Cnt = (nt + 8) >> 3;
    const int n0 = nt * 64;
    const float* base = &g_part[(size_t)((nt * 4) * 8 + mt) * 8192 + sub * 2048];
    const int row0 = mt * 128 + sub * 32;
    for (int e = threadIdx.x * 4; e < 2048; e += 1024) {
        float4 s = *reinterpret_cast<const float4*>(&base[e]);
        for (int c = 1; c < Cnt; c++) {
            float4 p = *reinterpret_cast<const float4*>(&base[(size_t)c * 65536 + e]);
            s.x += p.x; s.y += p.y; s.z += p.z; s.w += p.w;
        }
        int m = e >> 6, n = e & 63;
        float4 bv = *reinterpret_cast<const float4*>(&bias[n0 + n]);
        float4 o;
        o.x = tanhf(s.x + bv.x); o.y = tanhf(s.y + bv.y);
        o.z = tanhf(s.z + bv.z); o.w = tanhf(s.w + bv.w);
        *reinterpret_cast<float4*>(&g_t2[(row0 + m) * 2048 + n0 + n]) = o;
    }
}

// ---------------- layer 2: h2 partials = t2 @ wn2^T (K-split x2) ----------------
__global__ void __launch_bounds__(256) layer2_kernel(int f) {
    __shared__ float ts[16][68];
    int tid = threadIdx.x;
    int o = tid & 63;
    int bq = tid >> 6;
    int bbase = blockIdx.x * 16;
    int kbase = blockIdx.y * 1024;
    const float* wn2K = g_wn2K[f];
    float acc[4] = {};
    for (int k0 = kbase; k0 < kbase + 1024; k0 += 64) {
        {
            int rr = tid >> 4, cq = tid & 15;
            float4 v = *reinterpret_cast<const float4*>(&g_t2[(bbase + rr) * 2048 + k0 + cq * 4]);
            *reinterpret_cast<float4*>(&ts[rr][cq * 4]) = v;
        }
        __syncthreads();
        #pragma unroll
        for (int kq = 0; kq < 16; kq++) {
            float4 w = *reinterpret_cast<const float4*>(&wn2K[o * 2048 + k0 + kq * 4]);
            #pragma unroll
            for (int j = 0; j < 4; j++) {
                float4 t = *reinterpret_cast<const float4*>(&ts[bq * 4 + j][kq * 4]);
                acc[j] = fmaf(w.x, t.x, acc[j]);
                acc[j] = fmaf(w.y, t.y, acc[j]);
                acc[j] = fmaf(w.z, t.z, acc[j]);
                acc[j] = fmaf(w.w, t.w, acc[j]);
            }
        }
        __syncthreads();
    }
    #pragma unroll
    for (int j = 0; j < 4; j++)
        g_h2[blockIdx.y * 65536 + (bbase + bq * 4 + j) * 64 + o] = acc[j];
}

// ---------------- Jacobian chain + gate + flip ----------------
__global__ void __launch_bounds__(256) jac_kernel(const float* __restrict__ xext,
                                                  int xsel, int nsel, int f,
                                                  const float* __restrict__ gate,
                                                  int hasGate, int accum,
                                                  const float* __restrict__ b2) {
    __shared__ float eg1s[1024];
    __shared__ float eg0s[32];
    __shared__ float eg2s[32];
    int d = blockIdx.x;
    int lane = threadIdx.x & 31, w = threadIdx.x >> 5;
    for (int i = threadIdx.x; i < 1024; i += 256) eg1s[i] = g_eg1[f][d * 1024 + i];
    if (threadIdx.x < 32) {
        eg0s[threadIdx.x] = g_eg0[f][d * 32 + threadIdx.x];
        eg2s[threadIdx.x] = g_eg2[f][d * 32 + threadIdx.x];
    }
    __syncthreads();
    const float* xcur = (xsel == 0) ? xext : ((xsel == 1) ? (const float*)g_xA : (const float*)g_xB);
    float* xnext = (nsel == 1) ? g_xA : g_xB;
    float gt = 0.f;
    if (hasGate) gt = *gate;
    float bias_d = b2[d];

    for (int bi = 0; bi < 16; bi++) {
        int b = blockIdx.y * 128 + bi * 8 + w;
        int idx = b * 2048 + d * 32 + lane;
        float t1v = __bfloat162float(g_t1h[idx]) + __bfloat162float(g_t1l[idx]);
        float v0 = eg0s[lane] * (1.f - t1v * t1v);
        float acc = 0.f;
        #pragma unroll
        for (int k = 0; k < 32; k++)
            acc = fmaf(eg1s[k * 32 + lane], __shfl_sync(WARP_FULL, v0, k), acc);
        float t2v = g_t2[idx];
        float term = eg2s[lane] * acc * (1.f - t2v * t2v);
        #pragma unroll
        for (int off = 16; off; off >>= 1) term += __shfl_xor_sync(WARP_FULL, term, off);

        if (lane == 0) {
            float g = logf(term);
            float outv = g_h2[b * 64 + d] + g_h2[65536 + b * 64 + d] + bias_d;
            float l;
            if (hasGate) {
                float z = g + gt;
                float sp1 = (z  > 20.f) ? z  : log1pf(expf(z));
                float sp0 = (gt > 20.f) ? gt : log1pf(expf(gt));
                l = sp1 - sp0;
                float sgm = 1.f / (1.f + expf(-gt));
                xnext[b * 64 + (63 - d)] = sgm * outv + (1.f - sgm) * xcur[b * 64 + d];
            } else {
                l = g;
                xnext[b * 64 + d] = outv;
            }
            if (accum) g_lterm[b * 64 + d] += l;
            else       g_lterm[b * 64 + d]  = l;
        }
    }
}

// ---------------- final reduction ----------------
__global__ void __launch_bounds__(256) final_kernel(int xsel, float* __restrict__ out) {
    const float* xf = (xsel == 1) ? (const float*)g_xA : (const float*)g_xB;
    int b = blockIdx.x * 8 + (threadIdx.x >> 5);
    int lane = threadIdx.x & 31;
    float v1 = xf[b * 64 + lane];
    float v2 = xf[b * 64 + 32 + lane];
    float s = -0.5f * (v1 * v1 + v2 * v2)
              + g_lterm[b * 64 + lane] + g_lterm[b * 64 + 32 + lane];
    #pragma unroll
    for (int off = 16; off; off >>= 1) s += __shfl_xor_sync(WARP_FULL, s, off);
    if (lane == 0) out[b] = s - 32.f * 1.8378770664093453f;
}

// ---------------- launch ----------------
extern "C" void kernel_launch(void* const* d_in, const int* in_sizes, int n_in,
                              void* d_out, int out_size) {
    (void)in_sizes; (void)n_in; (void)out_size;
    const float* x     = (const float*)d_in[0];
    const float* gate0 = (const float*)d_in[28];
    const float* gate1 = (const float*)d_in[29];

    static int smem_set = 0;
    if (!smem_set) {
        cudaFuncSetAttribute(layer1_mma_kernel,
                             cudaFuncAttributeMaxDynamicSharedMemorySize, L1_SMEM_BYTES);
        smem_set = 1;
    }

    PrepPtrs P;
    for (int f = 0; f < 3; f++)
        for (int l = 0; l < 3; l++) {
            P.W [f * 3 + l] = (const float*)d_in[1 + f * 9 + l * 3 + 0];
            P.dw[f * 3 + l] = (const float*)d_in[1 + f * 9 + l * 3 + 1];
        }
    prep_all_kernel<<<dim3(520, 3), 256>>>(P);

    int xsel = 0;
    for (int f = 0; f < 3; f++) {
        const float* b0 = (const float*)d_in[1 + f * 9 + 2];
        const float* b1 = (const float*)d_in[1 + f * 9 + 5];
        const float* b2 = (const float*)d_in[1 + f * 9 + 8];

        layer0_kernel<<<dim3(8, 128), 256>>>(x, xsel, f, b0);
        layer1_mma_kernel<<<dim3(32, 8, 4), 256, L1_SMEM_BYTES>>>(f);
        reduce1_kernel<<<dim3(32, 32), 256>>>(b1);
        layer2_kernel<<<dim3(64, 2), 256>>>(f);

        const float* gate = (f == 0) ? gate0 : ((f == 1) ? gate1 : nullptr);
        int nsel = (f & 1) ? 2 : 1;
        jac_kernel<<<dim3(64, 8), 256>>>(x, xsel, nsel, f, gate, (f < 2) ? 1 : 0, (f > 0) ? 1 : 0, b2);
        xsel = nsel;
    }
    final_kernel<<<128, 256>>>(xsel, (float*)d_out);
}

// round 8
// speedup vs baseline: 4.4154x; 1.1963x over previous
#include <cuda_runtime.h>
#include <cuda_fp16.h>
#include <math.h>
#include <stdint.h>

#define WARP_FULL 0xFFFFFFFFu

// ---------------- scratch (device globals; no allocation) ----------------
__device__ float  g_wn0T[3][64 * 2048];
__device__ __half g_wn1f[3][2048 * 2048];   // [f][n][k] fp16 weights
__device__ float  g_wn2K[3][64 * 2048];
__device__ float  g_eg0 [3][2048];
__device__ float  g_eg1 [3][64 * 32 * 32];
__device__ float  g_eg2 [3][64 * 32];
__device__ float  g_t1 [1024 * 2048];       // fp32 t1 (jac path)
__device__ __half g_t1f[1024 * 2048];       // fp16 t1 (GEMM path)
__device__ float  g_t2 [1024 * 2048];
__device__ float  g_part[32 * 4 * 8 * 8192];  // [(nt*4+ch)*8+mt][m 128][n 64]
__device__ float  g_h2 [2 * 1024 * 64];
__device__ float  g_xA [1024 * 64];
__device__ float  g_xB [1024 * 64];
__device__ float  g_lterm[1024 * 64];

struct PrepPtrs { const float* W[9]; const float* dw[9]; };

__device__ __forceinline__ void mma16816(float* c, const uint32_t* a, const uint32_t* b) {
    asm volatile("mma.sync.aligned.m16n8k16.row.col.f32.f16.f16.f32 "
        "{%0,%1,%2,%3}, {%4,%5,%6,%7}, {%8,%9}, {%0,%1,%2,%3};"
        : "+f"(c[0]), "+f"(c[1]), "+f"(c[2]), "+f"(c[3])
        : "r"(a[0]), "r"(a[1]), "r"(a[2]), "r"(a[3]), "r"(b[0]), "r"(b[1]));
}
__device__ __forceinline__ uint32_t smem_u32(const void* p) {
    uint32_t a;
    asm("{ .reg .u64 t; cvta.to.shared.u64 t, %1; cvt.u32.u64 %0, t; }" : "=r"(a) : "l"(p));
    return a;
}
__device__ __forceinline__ void cp16(uint32_t dst, const void* src) {
    asm volatile("cp.async.cg.shared.global [%0], [%1], 16;" :: "r"(dst), "l"(src));
}
#define CP_COMMIT() asm volatile("cp.async.commit_group;" ::: "memory")
#define CP_WAIT(n)  asm volatile("cp.async.wait_group %0;" :: "n"(n) : "memory")

// ---------------- merged weight preprocessing: warp per row ----------------
__global__ void __launch_bounds__(256) prep_all_kernel(PrepPtrs P) {
    int f = blockIdx.y;
    int wr = blockIdx.x * 8 + (threadIdx.x >> 5);
    int lane = threadIdx.x & 31;

    if (wr < 2048) {                        // ---- layer0
        const float* W  = P.W [f * 3 + 0];
        const float* dw = P.dw[f * 3 + 0];
        int r = wr, blk = r >> 5;
        float vals[2]; float s = 0.f;
        #pragma unroll
        for (int i = 0; i < 2; i++) {
            int c = lane + 32 * i;
            float raw = W[r * 64 + c];
            float v = (c < blk) ? raw : ((c == blk) ? expf(raw) : 0.f);
            vals[i] = v; s += v * v;
        }
        #pragma unroll
        for (int off = 16; off; off >>= 1) s += __shfl_xor_sync(WARP_FULL, s, off);
        float scale = expf(dw[r]) * rsqrtf(s);
        #pragma unroll
        for (int i = 0; i < 2; i++) {
            int c = lane + 32 * i;
            float wv = vals[i] * scale;
            g_wn0T[f][c * 2048 + r] = wv;
            if (c == blk) g_eg0[f][r] = wv;
        }
    } else if (wr < 4096) {                 // ---- layer1 (fp16)
        const float* W  = P.W [f * 3 + 1];
        const float* dw = P.dw[f * 3 + 1];
        int r = wr - 2048, blk = r >> 5;
        int d0 = blk * 32, d1 = d0 + 32;
        int cmax = ((r >> 6) + 1) << 6;
        float s = 0.f;
        for (int c = lane; c < d1; c += 32) {
            float wv = W[r * 2048 + c];
            if (c >= d0) wv = expf(wv);
            s += wv * wv;
        }
        #pragma unroll
        for (int off = 16; off; off >>= 1) s += __shfl_xor_sync(WARP_FULL, s, off);
        float scale = expf(dw[r]) * rsqrtf(s);
        for (int c = lane; c < cmax; c += 32) {
            float o;
            if (c < d0)       o = W[r * 2048 + c] * scale;
            else if (c < d1) {
                o = expf(W[r * 2048 + c]) * scale;
                g_eg1[f][blk * 1024 + (c - d0) * 32 + (r & 31)] = o;
            } else            o = 0.f;
            g_wn1f[f][r * 2048 + c] = __float2half(o);
        }
    } else {                                // ---- layer2
        const float* W  = P.W [f * 3 + 2];
        const float* dw = P.dw[f * 3 + 2];
        int r = wr - 4096;
        int d0 = r * 32, d1 = d0 + 32;
        float s = 0.f;
        for (int c = lane; c < d1; c += 32) {
            float wv = W[r * 2048 + c];
            if (c >= d0) wv = expf(wv);
            s += wv * wv;
        }
        #pragma unroll
        for (int off = 16; off; off >>= 1) s += __shfl_xor_sync(WARP_FULL, s, off);
        float scale = expf(dw[r]) * rsqrtf(s);
        for (int c = lane; c < 2048; c += 32) {
            float o;
            if (c < d0)       o = W[r * 2048 + c] * scale;
            else if (c < d1) {
                o = expf(W[r * 2048 + c]) * scale;
                g_eg2[f][r * 32 + (c - d0)] = o;
            } else            o = 0.f;
            g_wn2K[f][r * 2048 + c] = o;
        }
    }
}

// ---------------- layer 0: t1 = tanh(x @ wn0^T + b0) -> fp32 + fp16 ----------------
__global__ void __launch_bounds__(256) layer0_kernel(const float* __restrict__ xext,
                                                     int xsel, int f,
                                                     const float* __restrict__ bias) {
    __shared__ float xs[64][8];
    const float* xsrc = (xsel == 0) ? xext : ((xsel == 1) ? (const float*)g_xA : (const float*)g_xB);
    int o = blockIdx.x * 256 + threadIdx.x;
    int bbase = blockIdx.y * 8;
    for (int i = threadIdx.x; i < 512; i += 256) {
        int k = i >> 3, bi = i & 7;
        xs[k][bi] = xsrc[(bbase + bi) * 64 + k];
    }
    __syncthreads();
    const float* wn0T = g_wn0T[f];
    float bv = bias[o];
    float acc[8];
    #pragma unroll
    for (int bi = 0; bi < 8; bi++) acc[bi] = bv;
    #pragma unroll 16
    for (int k = 0; k < 64; k++) {
        float w = wn0T[k * 2048 + o];
        float4 x0 = *reinterpret_cast<const float4*>(&xs[k][0]);
        float4 x1 = *reinterpret_cast<const float4*>(&xs[k][4]);
        acc[0] = fmaf(x0.x, w, acc[0]); acc[1] = fmaf(x0.y, w, acc[1]);
        acc[2] = fmaf(x0.z, w, acc[2]); acc[3] = fmaf(x0.w, w, acc[3]);
        acc[4] = fmaf(x1.x, w, acc[4]); acc[5] = fmaf(x1.y, w, acc[5]);
        acc[6] = fmaf(x1.z, w, acc[6]); acc[7] = fmaf(x1.w, w, acc[7]);
    }
    #pragma unroll
    for (int bi = 0; bi < 8; bi++) {
        float t = tanhf(acc[bi]);
        int idx = (bbase + bi) * 2048 + o;
        g_t1[idx]  = t;
        g_t1f[idx] = __float2half(t);
    }
}

// ---------------- layer 1: fp16 HMMA GEMM -> fp32 partials ----------------
// grid (32 nt, 8 mt, 4 ch), 256 threads (8 warps). BM=128, BN=64, chunk=32.
// Smem row stride 40 halves (conflict-free LDS.32 fragments).
#define L1_A 0
#define L1_B (128 * 40)
#define L1_BUF (192 * 40)                 // 7680 halves / buffer
#define L1_SMEM_BYTES (2 * L1_BUF * 2)    // 30720 bytes

__global__ void __launch_bounds__(256) layer1_mma_kernel(int f) {
    const int nt = blockIdx.x, mt = blockIdx.y, ch = blockIdx.z;
    const int Klim = (nt + 1) * 64;
    const int kbeg = ch * 512;
    if (kbeg >= Klim) return;
    const int kend = min(kbeg + 512, Klim);
    const int m0 = mt * 128, n0 = nt * 64;

    extern __shared__ __half smh[];
    const uint32_t sb = smem_u32(smh);

    const int tid = threadIdx.x;
    const int w = tid >> 5, l = tid & 31;
    const int mw = (w & 3) * 32, nw = (w >> 2) * 32;
    const int lr = l >> 2, lc2 = (l & 3) * 2;

    const __half* t1f = g_t1f;
    const __half* w1f = g_wn1f[f];

    const int ra = tid >> 2, qa = (tid & 3) * 8;   // A rows 0..63 (+64), B rows 0..63

    auto load_chunk = [&](uint32_t base, int kc) {
        cp16(base + (uint32_t)(L1_A + ra * 40 + qa) * 2,        &t1f[(m0 + ra) * 2048 + kc + qa]);
        cp16(base + (uint32_t)(L1_A + (ra + 64) * 40 + qa) * 2, &t1f[(m0 + ra + 64) * 2048 + kc + qa]);
        cp16(base + (uint32_t)(L1_B + ra * 40 + qa) * 2,        &w1f[(n0 + ra) * 2048 + kc + qa]);
        CP_COMMIT();
    };

    float acc[2][4][4] = {};

    load_chunk(sb, kbeg);
    int buf = 0;
    for (int kc = kbeg; kc < kend; kc += 32) {
        bool more = (kc + 32) < kend;
        if (more) load_chunk(sb + (uint32_t)(buf ^ 1) * L1_BUF * 2, kc + 32);
        if (more) { CP_WAIT(1); } else { CP_WAIT(0); }
        __syncthreads();

        const __half* S = smh + buf * L1_BUF;
        #pragma unroll
        for (int kk = 0; kk < 32; kk += 16) {
            uint32_t a[2][4], b[4][2];
            #pragma unroll
            for (int i = 0; i < 2; i++) {
                int R = mw + i * 16 + lr;
                a[i][0] = *(const uint32_t*)&S[L1_A + R * 40 + kk + lc2];
                a[i][1] = *(const uint32_t*)&S[L1_A + (R + 8) * 40 + kk + lc2];
                a[i][2] = *(const uint32_t*)&S[L1_A + R * 40 + kk + 8 + lc2];
                a[i][3] = *(const uint32_t*)&S[L1_A + (R + 8) * 40 + kk + 8 + lc2];
            }
            #pragma unroll
            for (int j = 0; j < 4; j++) {
                int N = nw + j * 8 + lr;
                b[j][0] = *(const uint32_t*)&S[L1_B + N * 40 + kk + lc2];
                b[j][1] = *(const uint32_t*)&S[L1_B + N * 40 + kk + 8 + lc2];
            }
            #pragma unroll
            for (int i = 0; i < 2; i++)
                #pragma unroll
                for (int j = 0; j < 4; j++)
                    mma16816(acc[i][j], a[i], b[j]);
        }
        __syncthreads();
        buf ^= 1;
    }

    float* out = &g_part[(size_t)((nt * 4 + ch) * 8 + mt) * 8192];
    #pragma unroll
    for (int i = 0; i < 2; i++) {
        int r = mw + i * 16 + lr;
        #pragma unroll
        for (int j = 0; j < 4; j++) {
            int n = nw + j * 8 + lc2;
            *reinterpret_cast<float2*>(&out[r * 64 + n])       = make_float2(acc[i][j][0], acc[i][j][1]);
            *reinterpret_cast<float2*>(&out[(r + 8) * 64 + n]) = make_float2(acc[i][j][2], acc[i][j][3]);
        }
    }
}

// ---------------- layer1 reduce: t2 = tanh(sum partials + b1) ----------------
__global__ void __launch_bounds__(256) reduce1_kernel(const float* __restrict__ bias) {
    const int nt = blockIdx.x, ms = blockIdx.y;
    const int mt = ms >> 2, sub = ms & 3;
    const int Cnt = (nt + 8) >> 3;
    const int n0 = nt * 64;
    const float* base = &g_part[(size_t)((nt * 4) * 8 + mt) * 8192 + sub * 2048];
    const int row0 = mt * 128 + sub * 32;
    for (int e = threadIdx.x * 4; e < 2048; e += 1024) {
        float4 s = *reinterpret_cast<const float4*>(&base[e]);
        for (int c = 1; c < Cnt; c++) {
            float4 p = *reinterpret_cast<const float4*>(&base[(size_t)c * 65536 + e]);
            s.x += p.x; s.y += p.y; s.z += p.z; s.w += p.w;
        }
        int m = e >> 6, n = e & 63;
        float4 bv = *reinterpret_cast<const float4*>(&bias[n0 + n]);
        float4 o;
        o.x = tanhf(s.x + bv.x); o.y = tanhf(s.y + bv.y);
        o.z = tanhf(s.z + bv.z); o.w = tanhf(s.w + bv.w);
        *reinterpret_cast<float4*>(&g_t2[(row0 + m) * 2048 + n0 + n]) = o;
    }
}

// ---------------- layer 2: h2 partials = t2 @ wn2^T (K-split x2) ----------------
__global__ void __launch_bounds__(256) layer2_kernel(int f) {
    __shared__ float ts[16][68];
    int tid = threadIdx.x;
    int o = tid & 63;
    int bq = tid >> 6;
    int bbase = blockIdx.x * 16;
    int kbase = blockIdx.y * 1024;
    const float* wn2K = g_wn2K[f];
    float acc[4] = {};
    for (int k0 = kbase; k0 < kbase + 1024; k0 += 64) {
        {
            int rr = tid >> 4, cq = tid & 15;
            float4 v = *reinterpret_cast<const float4*>(&g_t2[(bbase + rr) * 2048 + k0 + cq * 4]);
            *reinterpret_cast<float4*>(&ts[rr][cq * 4]) = v;
        }
        __syncthreads();
        #pragma unroll
        for (int kq = 0; kq < 16; kq++) {
            float4 w = *reinterpret_cast<const float4*>(&wn2K[o * 2048 + k0 + kq * 4]);
            #pragma unroll
            for (int j = 0; j < 4; j++) {
                float4 t = *reinterpret_cast<const float4*>(&ts[bq * 4 + j][kq * 4]);
                acc[j] = fmaf(w.x, t.x, acc[j]);
                acc[j] = fmaf(w.y, t.y, acc[j]);
                acc[j] = fmaf(w.z, t.z, acc[j]);
                acc[j] = fmaf(w.w, t.w, acc[j]);
            }
        }
        __syncthreads();
    }
    #pragma unroll
    for (int j = 0; j < 4; j++)
        g_h2[blockIdx.y * 65536 + (bbase + bq * 4 + j) * 64 + o] = acc[j];
}

// ---------------- Jacobian chain + gate + flip ----------------
__global__ void __launch_bounds__(256) jac_kernel(const float* __restrict__ xext,
                                                  int xsel, int nsel, int f,
                                                  const float* __restrict__ gate,
                                                  int hasGate, int accum,
                                                  const float* __restrict__ b2) {
    __shared__ float eg1s[1024];
    __shared__ float eg0s[32];
    __shared__ float eg2s[32];
    int d = blockIdx.x;
    int lane = threadIdx.x & 31, w = threadIdx.x >> 5;
    for (int i = threadIdx.x; i < 1024; i += 256) eg1s[i] = g_eg1[f][d * 1024 + i];
    if (threadIdx.x < 32) {
        eg0s[threadIdx.x] = g_eg0[f][d * 32 + threadIdx.x];
        eg2s[threadIdx.x] = g_eg2[f][d * 32 + threadIdx.x];
    }
    __syncthreads();
    const float* xcur = (xsel == 0) ? xext : ((xsel == 1) ? (const float*)g_xA : (const float*)g_xB);
    float* xnext = (nsel == 1) ? g_xA : g_xB;
    float gt = 0.f;
    if (hasGate) gt = *gate;
    float bias_d = b2[d];

    for (int bi = 0; bi < 16; bi++) {
        int b = blockIdx.y * 128 + bi * 8 + w;
        int idx = b * 2048 + d * 32 + lane;
        float t1v = g_t1[idx];
        float v0 = eg0s[lane] * (1.f - t1v * t1v);
        float acc = 0.f;
        #pragma unroll
        for (int k = 0; k < 32; k++)
            acc = fmaf(eg1s[k * 32 + lane], __shfl_sync(WARP_FULL, v0, k), acc);
        float t2v = g_t2[idx];
        float term = eg2s[lane] * acc * (1.f - t2v * t2v);
        #pragma unroll
        for (int off = 16; off; off >>= 1) term += __shfl_xor_sync(WARP_FULL, term, off);

        if (lane == 0) {
            float g = logf(term);
            float outv = g_h2[b * 64 + d] + g_h2[65536 + b * 64 + d] + bias_d;
            float l;
            if (hasGate) {
                float z = g + gt;
                float sp1 = (z  > 20.f) ? z  : log1pf(expf(z));
                float sp0 = (gt > 20.f) ? gt : log1pf(expf(gt));
                l = sp1 - sp0;
                float sgm = 1.f / (1.f + expf(-gt));
                xnext[b * 64 + (63 - d)] = sgm * outv + (1.f - sgm) * xcur[b * 64 + d];
            } else {
                l = g;
                xnext[b * 64 + d] = outv;
            }
            if (accum) g_lterm[b * 64 + d] += l;
            else       g_lterm[b * 64 + d]  = l;
        }
    }
}

// ---------------- final reduction ----------------
__global__ void __launch_bounds__(256) final_kernel(int xsel, float* __restrict__ out) {
    const float* xf = (xsel == 1) ? (const float*)g_xA : (const float*)g_xB;
    int b = blockIdx.x * 8 + (threadIdx.x >> 5);
    int lane = threadIdx.x & 31;
    float v1 = xf[b * 64 + lane];
    float v2 = xf[b * 64 + 32 + lane];
    float s = -0.5f * (v1 * v1 + v2 * v2)
              + g_lterm[b * 64 + lane] + g_lterm[b * 64 + 32 + lane];
    #pragma unroll
    for (int off = 16; off; off >>= 1) s += __shfl_xor_sync(WARP_FULL, s, off);
    if (lane == 0) out[b] = s - 32.f * 1.8378770664093453f;
}

// ---------------- launch ----------------
extern "C" void kernel_launch(void* const* d_in, const int* in_sizes, int n_in,
                              void* d_out, int out_size) {
    (void)in_sizes; (void)n_in; (void)out_size;
    const float* x     = (const float*)d_in[0];
    const float* gate0 = (const float*)d_in[28];
    const float* gate1 = (const float*)d_in[29];

    PrepPtrs P;
    for (int f = 0; f < 3; f++)
        for (int l = 0; l < 3; l++) {
            P.W [f * 3 + l] = (const float*)d_in[1 + f * 9 + l * 3 + 0];
            P.dw[f * 3 + l] = (const float*)d_in[1 + f * 9 + l * 3 + 1];
        }
    prep_all_kernel<<<dim3(520, 3), 256>>>(P);

    int xsel = 0;
    for (int f = 0; f < 3; f++) {
        const float* b0 = (const float*)d_in[1 + f * 9 + 2];
        const float* b1 = (const float*)d_in[1 + f * 9 + 5];
        const float* b2 = (const float*)d_in[1 + f * 9 + 8];

        layer0_kernel<<<dim3(8, 128), 256>>>(x, xsel, f, b0);
        layer1_mma_kernel<<<dim3(32, 8, 4), 256, L1_SMEM_BYTES>>>(f);
        reduce1_kernel<<<dim3(32, 32), 256>>>(b1);
        layer2_kernel<<<dim3(64, 2), 256>>>(f);

        const float* gate = (f == 0) ? gate0 : ((f == 1) ? gate1 : nullptr);
        int nsel = (f & 1) ? 2 : 1;
        jac_kernel<<<dim3(64, 8), 256>>>(x, xsel, nsel, f, gate, (f < 2) ? 1 : 0, (f > 0) ? 1 : 0, b2);
        xsel = nsel;
    }
    final_kernel<<<128, 256>>>(xsel, (float*)d_out);
}